// round 9
// baseline (speedup 1.0000x reference)
#include <cuda_runtime.h>
#include <cuda_bf16.h>
#include <cstdint>

#define NSUM 2048
#define NMAX 64
#define MFEAT 16
#define HID 128
#define OUTF 64
#define NEDGE 16384
#define NLAYER 4
#define NROWS_TOTAL (NSUM * NMAX)
#define GRID_MAIN 296

// bf16 weight buffer layout (n-major, stride = 2K+8, [hi K | lo K | pad])
#define SZ_W1F (128 * 40)
#define SZ_WR  (128 * 264)
#define SZ_W2L (64 * 264)
#define OFF_W1F 0
#define OFF_W1R (SZ_W1F)
#define OFF_W2M (OFF_W1R + 3 * SZ_WR)
#define OFF_W2L (OFF_W2M + 3 * SZ_WR)
#define WBF_TOTAL (OFF_W2L + SZ_W2L)

// ---------------------------------------------------------------------------
// Device scratch (static __device__ globals: allocation-free per harness rules)
// ---------------------------------------------------------------------------
__device__ float g_X[(size_t)NSUM * NMAX * HID];
__device__ float g_H[(size_t)NSUM * NMAX * HID];
__device__ __nv_bfloat16 g_Wbf[WBF_TOTAL];
__device__ float g_stats[NLAYER * 2 * HID];
__device__ int   g_off[NSUM + 1];
__device__ int   g_csr[NEDGE];

// ---------------------------------------------------------------------------
// Setup kernel (launch #1): CTA 0 builds CSR (count/scan/fill) + zeroes stats;
// CTAs 1..106 convert weights fp32 -> bf16 hi/lo n-major.
// ---------------------------------------------------------------------------
__global__ void __launch_bounds__(1024)
gin_setup(const int* __restrict__ src, const int* __restrict__ dst,
          const float* __restrict__ W1f, const float* __restrict__ W1r,
          const float* __restrict__ W2m, const float* __restrict__ W2l)
{
    const int t = threadIdx.x;            // 1024 threads
    if (blockIdx.x != 0) {
        int idx = (blockIdx.x - 1) * 1024 + t;   // 106*1024 = 108544 exactly
        float w; int k, n, K; size_t doff; int sa;
        if (idx < 2048) {
            K = 16; k = idx / 128; n = idx % 128;
            w = W1f[idx]; doff = OFF_W1F; sa = 40;
        } else if (idx < 2048 + 3 * 16384) {
            int e = idx - 2048; int l = e / 16384; int r = e % 16384;
            K = 128; k = r / 128; n = r % 128;
            w = W1r[e]; doff = OFF_W1R + (size_t)l * SZ_WR; sa = 264;
        } else if (idx < 2048 + 6 * 16384) {
            int e = idx - 2048 - 3 * 16384; int l = e / 16384; int r = e % 16384;
            K = 128; k = r / 128; n = r % 128;
            w = W2m[e]; doff = OFF_W2M + (size_t)l * SZ_WR; sa = 264;
        } else {
            int e = idx - 2048 - 6 * 16384;
            K = 128; k = e / 64; n = e % 64;
            w = W2l[e]; doff = OFF_W2L; sa = 264;
        }
        __nv_bfloat16 hi = __float2bfloat16(w);
        __nv_bfloat16 lo = __float2bfloat16(w - __bfloat162float(hi));
        g_Wbf[doff + (size_t)n * sa + k]     = hi;
        g_Wbf[doff + (size_t)n * sa + K + k] = lo;
        return;
    }

    // ---- CSR build (single CTA) ----
    __shared__ int s0[NSUM], s1[NSUM], cur[NSUM];
    g_stats[t] = 0.f;                     // 4*2*128 == 1024 exactly
    #pragma unroll
    for (int j = 0; j < 2; j++) { s0[t + j * 1024] = 0; cur[t + j * 1024] = 0; }
    __syncthreads();

    #pragma unroll
    for (int j = 0; j < NEDGE / 1024; j++)
        atomicAdd(&s0[dst[t + j * 1024]], 1);
    __syncthreads();

    int* in = s0; int* out = s1;
    for (int d = 1; d < NSUM; d <<= 1) {
        #pragma unroll
        for (int j = 0; j < 2; j++) {
            int i = t + j * 1024;
            int v = in[i];
            if (i >= d) v += in[i - d];
            out[i] = v;
        }
        __syncthreads();
        int* tmp = in; in = out; out = tmp;
    }
    if (t == 0) g_off[0] = 0;
    #pragma unroll
    for (int j = 0; j < 2; j++) g_off[t + j * 1024 + 1] = in[t + j * 1024];
    __syncthreads();

    #pragma unroll
    for (int j = 0; j < NEDGE / 1024; j++) {
        int e = t + j * 1024;
        int d = dst[e];
        int p = atomicAdd(&cur[d], 1);
        int off = d ? in[d - 1] : 0;
        g_csr[off + p] = src[e];
    }
}

// ---------------------------------------------------------------------------
// MMA helpers
// ---------------------------------------------------------------------------
__device__ __forceinline__ void ldsm4(uint32_t* r, uint32_t a)
{
    asm volatile("ldmatrix.sync.aligned.m8n8.x4.shared.b16 {%0,%1,%2,%3}, [%4];"
                 : "=r"(r[0]), "=r"(r[1]), "=r"(r[2]), "=r"(r[3]) : "r"(a));
}

__device__ __forceinline__ void mma_bf16(float* d, const uint32_t* a, uint32_t b0, uint32_t b1)
{
    asm volatile("mma.sync.aligned.m16n8k16.row.col.f32.bf16.bf16.f32 "
                 "{%0,%1,%2,%3},{%4,%5,%6,%7},{%8,%9},{%0,%1,%2,%3};"
                 : "+f"(d[0]), "+f"(d[1]), "+f"(d[2]), "+f"(d[3])
                 : "r"(a[0]), "r"(a[1]), "r"(a[2]), "r"(a[3]), "r"(b0), "r"(b1));
}

// hi/lo bf16 convert + store of a float4 row-chunk
__device__ __forceinline__ void cvt_store(__nv_bfloat16* dhi, __nv_bfloat16* dlo, float4 v)
{
    __nv_bfloat16 h0 = __float2bfloat16(v.x), h1 = __float2bfloat16(v.y);
    __nv_bfloat16 h2 = __float2bfloat16(v.z), h3 = __float2bfloat16(v.w);
    __nv_bfloat162 a; a.x = h0; a.y = h1;
    __nv_bfloat162 b; b.x = h2; b.y = h3;
    ((__nv_bfloat162*)dhi)[0] = a; ((__nv_bfloat162*)dhi)[1] = b;
    __nv_bfloat162 c, d;
    c.x = __float2bfloat16(v.x - __bfloat162float(h0));
    c.y = __float2bfloat16(v.y - __bfloat162float(h1));
    d.x = __float2bfloat16(v.z - __bfloat162float(h2));
    d.y = __float2bfloat16(v.w - __bfloat162float(h3));
    ((__nv_bfloat162*)dlo)[0] = c; ((__nv_bfloat162*)dlo)[1] = d;
}

// GEMM core: 3 segments (hi*hi + lo*hi + hi*lo), KH/16 ksteps each.
template <int KH, int MT>
__device__ __forceinline__ void gemm_mma(const uint32_t* aBase, const uint32_t* bBase,
                                         int kaSel, int kbSel, float (*acc)[4][4])
{
    #pragma unroll
    for (int seg = 0; seg < 3; seg++) {
        const int aoff = (seg == 1) ? KH : 0;
        const int boff = (seg == 2) ? KH : 0;
        #pragma unroll
        for (int ks = 0; ks < KH / 16; ks++) {
            const int ka = (aoff + ks * 16 + kaSel) * 2;
            const int kb = (boff + ks * 16 + kbSel) * 2;
            uint32_t a[MT][4], b[2][4];
            #pragma unroll
            for (int mi = 0; mi < MT; mi++) ldsm4(a[mi], aBase[mi] + ka);
            #pragma unroll
            for (int p = 0; p < 2; p++) ldsm4(b[p], bBase[p] + kb);
            #pragma unroll
            for (int mi = 0; mi < MT; mi++)
                #pragma unroll
                for (int ni = 0; ni < 4; ni++)
                    mma_bf16(acc[mi][ni], a[mi], b[ni >> 1][(ni & 1) * 2], b[ni >> 1][(ni & 1) * 2 + 1]);
        }
    }
}

// ---------------------------------------------------------------------------
// Kernel A: gather + (1+eps)X + GEMM1, software-pipelined:
//   gather(n+1) [memory] shares the barrier region with GEMM(n) [tensor]
// ---------------------------------------------------------------------------
template <int KH>
__global__ void __launch_bounds__(256, 2)
gin_A(const float* __restrict__ Xin, const __nv_bfloat16* __restrict__ Wg,
      const float* __restrict__ b1, const float* __restrict__ epsArr, int layer,
      float* __restrict__ Hout, float* __restrict__ gsum, float* __restrict__ gsq)
{
    constexpr int SA  = 2 * KH + 8;
    constexpr int KC4 = KH / 4;
    constexpr int EPT = 64 * KC4 / 256;
    extern __shared__ float smf[];
    __nv_bfloat16* Ws = (__nv_bfloat16*)smf;     // 128*SA
    __nv_bfloat16* As = Ws + 128 * SA;           // 64*SA
    float* sb = (float*)(As + 64 * SA);          // 128

    const int tid  = threadIdx.x;
    const int lane = tid & 31, wid = tid >> 5;
    const int wm = wid & 1, wn = wid >> 1;       // 2 (m) x 4 (n) warps
    const int grp = lane >> 2, tig = lane & 3;
    const int sel = lane >> 3, l7 = lane & 7;
    const float epl = 1.f + epsArr[layer];

    {   // stage weights + bias
        const uint4* s = (const uint4*)Wg;
        uint4* d = (uint4*)Ws;
        for (int i = tid; i < 128 * SA / 8; i += 256) d[i] = s[i];
        if (tid < 128) sb[tid] = b1[tid];
    }

    uint32_t aBase[2], bBase[2];
    {
        uint32_t asb = (uint32_t)__cvta_generic_to_shared(As);
        uint32_t wsb = (uint32_t)__cvta_generic_to_shared(Ws);
        aBase[0] = asb + (uint32_t)((wm * 32 + l7 + (sel & 1) * 8) * SA) * 2;
        aBase[1] = aBase[0] + 16 * SA * 2;
        bBase[0] = wsb + (uint32_t)((wn * 32 + l7 + (sel >> 1) * 8) * SA) * 2;
        bBase[1] = bBase[0] + 16 * SA * 2;
    }
    const int kaSel = (sel >> 1) * 8, kbSel = (sel & 1) * 8;

    float psum[8], psq[8];
    #pragma unroll
    for (int q = 0; q < 8; q++) { psum[q] = 0.f; psq[q] = 0.f; }

    float4 r[EPT];
    auto gather = [&](int g) {
        const float4* xn = (const float4*)(Xin + (size_t)g * 64 * KH);
        #pragma unroll
        for (int j = 0; j < EPT; j++) {
            float4 v = xn[tid + j * 256];
            r[j].x = v.x * epl; r[j].y = v.y * epl; r[j].z = v.z * epl; r[j].w = v.w * epl;
        }
        const int eE = g_off[g + 1];
        for (int e = g_off[g]; e < eE; e++) {
            const float4* xs = (const float4*)(Xin + (size_t)g_csr[e] * 64 * KH);
            #pragma unroll
            for (int j = 0; j < EPT; j++) {
                float4 v = xs[tid + j * 256];
                r[j].x += v.x; r[j].y += v.y; r[j].z += v.z; r[j].w += v.w;
            }
        }
    };

    int n = blockIdx.x;
    gather(n);                             // prologue

    for (; n < NSUM; ) {
        __syncthreads();                   // previous GEMM done reading As
        #pragma unroll
        for (int j = 0; j < EPT; j++) {
            int i = tid + j * 256;
            int row = i / KC4, col = (i % KC4) * 4;
            cvt_store(&As[row * SA + col], &As[row * SA + KH + col], r[j]);
        }
        __syncthreads();                   // As ready

        const int nn = n + GRID_MAIN;
        if (nn < NSUM) gather(nn);         // memory work for next tile

        // ---- GEMM (tile n) ----
        float acc[2][4][4];
        #pragma unroll
        for (int mi = 0; mi < 2; mi++)
            #pragma unroll
            for (int ni = 0; ni < 4; ni++) {
                int c0 = wn * 32 + ni * 8 + tig * 2;
                acc[mi][ni][0] = sb[c0];     acc[mi][ni][1] = sb[c0 + 1];
                acc[mi][ni][2] = sb[c0];     acc[mi][ni][3] = sb[c0 + 1];
            }
        gemm_mma<KH, 2>(aBase, bBase, kaSel, kbSel, acc);

        // ---- epilogue: H + BN partials ----
        float* hb = Hout + (size_t)n * 64 * 128;
        #pragma unroll
        for (int mi = 0; mi < 2; mi++) {
            int r0 = wm * 32 + mi * 16 + grp;
            #pragma unroll
            for (int ni = 0; ni < 4; ni++) {
                int c0 = wn * 32 + ni * 8 + tig * 2;
                float2 v0 = make_float2(acc[mi][ni][0], acc[mi][ni][1]);
                float2 v1 = make_float2(acc[mi][ni][2], acc[mi][ni][3]);
                *(float2*)&hb[(size_t)r0 * 128 + c0]       = v0;
                *(float2*)&hb[(size_t)(r0 + 8) * 128 + c0] = v1;
                psum[ni * 2 + 0] += v0.x + v1.x;
                psum[ni * 2 + 1] += v0.y + v1.y;
                psq[ni * 2 + 0]  += v0.x * v0.x + v1.x * v1.x;
                psq[ni * 2 + 1]  += v0.y * v0.y + v1.y * v1.y;
            }
        }
        n = nn;
    }

    // ---- CTA-end BN reduction (shuffle, then global atomics) ----
    #pragma unroll
    for (int q = 0; q < 8; q++) {
        float s = psum[q], ss = psq[q];
        s  += __shfl_xor_sync(0xffffffffu, s, 4);
        s  += __shfl_xor_sync(0xffffffffu, s, 8);
        s  += __shfl_xor_sync(0xffffffffu, s, 16);
        ss += __shfl_xor_sync(0xffffffffu, ss, 4);
        ss += __shfl_xor_sync(0xffffffffu, ss, 8);
        ss += __shfl_xor_sync(0xffffffffu, ss, 16);
        if (lane < 4) {
            int c = wn * 32 + (q >> 1) * 8 + lane * 2 + (q & 1);
            atomicAdd(&gsum[c], s);
            atomicAdd(&gsq[c], ss);
        }
    }
}

// ---------------------------------------------------------------------------
// Kernel C: BN(params in-CTA) + ReLU + GEMM2, software-pipelined like A;
// LAST fuses masked PE reduction
// ---------------------------------------------------------------------------
template <int NOUT, bool LAST>
__global__ void __launch_bounds__(256, 2)
gin_C(const float* __restrict__ Hin, const __nv_bfloat16* __restrict__ Wg,
      const float* __restrict__ b2,
      const float* __restrict__ gsum, const float* __restrict__ gsq,
      const float* __restrict__ gamma, const float* __restrict__ beta,
      float* __restrict__ Xout, const float* __restrict__ mask, float* __restrict__ pe)
{
    constexpr int KH = 128, SA = 264;
    constexpr int WGM = (NOUT == 128) ? 2 : 4;
    constexpr int MT  = (NOUT == 128) ? 2 : 1;
    extern __shared__ float smf[];
    __nv_bfloat16* Ws = (__nv_bfloat16*)smf;     // NOUT*SA
    __nv_bfloat16* As = Ws + NOUT * SA;          // 64*SA
    float* sb  = (float*)(As + 64 * SA);         // NOUT
    float* ssc = sb + NOUT;                      // 128
    float* ssh = ssc + 128;                      // 128
    float* spe = ssh + 128;                      // 64 (LAST only)

    const int tid  = threadIdx.x;
    const int lane = tid & 31, wid = tid >> 5;
    const int wm = wid % WGM, wn = wid / WGM;
    const int grp = lane >> 2, tig = lane & 3;
    const int sel = lane >> 3, l7 = lane & 7;
    const int rowbase = wm * MT * 16, colbase = wn * 32;

    {
        const uint4* s = (const uint4*)Wg;
        uint4* d = (uint4*)Ws;
        for (int i = tid; i < NOUT * SA / 8; i += 256) d[i] = s[i];
        if (tid < NOUT) sb[tid] = b2[tid];
        if (tid < 128) {
            // BN finalize in-CTA
            const float inv = 1.f / (float)NROWS_TOTAL;
            float mu  = gsum[tid] * inv;
            float var = gsq[tid] * inv - mu * mu;
            float rs  = rsqrtf(var + 1e-5f);
            float scl = rs * gamma[tid];
            ssc[tid] = scl;
            ssh[tid] = beta[tid] - mu * scl;
        }
    }

    uint32_t aBase[MT], bBase[2];
    {
        uint32_t asb = (uint32_t)__cvta_generic_to_shared(As);
        uint32_t wsb = (uint32_t)__cvta_generic_to_shared(Ws);
        #pragma unroll
        for (int mi = 0; mi < MT; mi++)
            aBase[mi] = asb + (uint32_t)((rowbase + mi * 16 + l7 + (sel & 1) * 8) * SA) * 2;
        bBase[0] = wsb + (uint32_t)((colbase + l7 + (sel >> 1) * 8) * SA) * 2;
        bBase[1] = bBase[0] + 16 * SA * 2;
    }
    const int kaSel = (sel >> 1) * 8, kbSel = (sel & 1) * 8;

    float4 h[8];
    auto loadH = [&](int g) {
        const float4* h4 = (const float4*)(Hin + (size_t)g * 64 * 128);
        #pragma unroll
        for (int j = 0; j < 8; j++) h[j] = h4[tid + j * 256];
    };

    int n = blockIdx.x;
    loadH(n);                              // prologue

    for (; n < NSUM; ) {
        __syncthreads();                   // previous GEMM done reading As
        // ---- BN + ReLU + hi/lo convert into A ----
        #pragma unroll
        for (int j = 0; j < 8; j++) {
            int i = tid + j * 256;
            int row = i >> 5, col = (i & 31) * 4;
            float4 sc = *(const float4*)&ssc[col];
            float4 sh = *(const float4*)&ssh[col];
            float4 a;
            a.x = fmaxf(fmaf(h[j].x, sc.x, sh.x), 0.f);
            a.y = fmaxf(fmaf(h[j].y, sc.y, sh.y), 0.f);
            a.z = fmaxf(fmaf(h[j].z, sc.z, sh.z), 0.f);
            a.w = fmaxf(fmaf(h[j].w, sc.w, sh.w), 0.f);
            cvt_store(&As[row * SA + col], &As[row * SA + KH + col], a);
        }
        __syncthreads();                   // As ready

        const int nn = n + GRID_MAIN;
        if (nn < NSUM) loadH(nn);          // memory work for next tile

        // ---- GEMM (tile n) ----
        float acc[MT][4][4];
        #pragma unroll
        for (int mi = 0; mi < MT; mi++)
            #pragma unroll
            for (int ni = 0; ni < 4; ni++) {
                int c0 = colbase + ni * 8 + tig * 2;
                acc[mi][ni][0] = sb[c0];     acc[mi][ni][1] = sb[c0 + 1];
                acc[mi][ni][2] = sb[c0];     acc[mi][ni][3] = sb[c0 + 1];
            }
        gemm_mma<KH, MT>(aBase, bBase, kaSel, kbSel, acc);

        if (!LAST) {
            float* xb = Xout + (size_t)n * 64 * 128;
            #pragma unroll
            for (int mi = 0; mi < MT; mi++) {
                int r0 = rowbase + mi * 16 + grp;
                #pragma unroll
                for (int ni = 0; ni < 4; ni++) {
                    int c0 = colbase + ni * 8 + tig * 2;
                    *(float2*)&xb[(size_t)r0 * 128 + c0]       = make_float2(acc[mi][ni][0], acc[mi][ni][1]);
                    *(float2*)&xb[(size_t)(r0 + 8) * 128 + c0] = make_float2(acc[mi][ni][2], acc[mi][ni][3]);
                }
            }
        } else {
            if (tid < 64) spe[tid] = 0.f;
            __syncthreads();
            float m0 = mask[(size_t)n * 64 + rowbase + grp];
            float m1 = mask[(size_t)n * 64 + rowbase + grp + 8];
            #pragma unroll
            for (int ni = 0; ni < 4; ni++) {
                float p0 = m0 * acc[0][ni][0] + m1 * acc[0][ni][2];
                float p1 = m0 * acc[0][ni][1] + m1 * acc[0][ni][3];
                p0 += __shfl_xor_sync(0xffffffffu, p0, 4);
                p0 += __shfl_xor_sync(0xffffffffu, p0, 8);
                p0 += __shfl_xor_sync(0xffffffffu, p0, 16);
                p1 += __shfl_xor_sync(0xffffffffu, p1, 4);
                p1 += __shfl_xor_sync(0xffffffffu, p1, 8);
                p1 += __shfl_xor_sync(0xffffffffu, p1, 16);
                if (lane < 4) {
                    int c = colbase + ni * 8 + lane * 2;
                    atomicAdd(&spe[c], p0);
                    atomicAdd(&spe[c + 1], p1);
                }
            }
            __syncthreads();
            if (tid < 64) pe[(size_t)n * 64 + tid] = spe[tid];
        }
        n = nn;
    }
}

// ---------------------------------------------------------------------------
// Host-side launch
// ---------------------------------------------------------------------------
extern "C" void kernel_launch(void* const* d_in, const int* in_sizes, int n_in,
                              void* d_out, int out_size)
{
    const float* W        = (const float*)d_in[0];
    const float* mask     = (const float*)d_in[1];
    const int*   src      = (const int*)d_in[2];
    const int*   dst      = (const int*)d_in[3];
    const float* eps      = (const float*)d_in[4];
    const float* W1_first = (const float*)d_in[5];
    const float* b1_first = (const float*)d_in[6];
    const float* W1_rest  = (const float*)d_in[7];
    const float* b1_rest  = (const float*)d_in[8];
    const float* bn_gamma = (const float*)d_in[9];
    const float* bn_beta  = (const float*)d_in[10];
    const float* W2_mid   = (const float*)d_in[11];
    const float* b2_mid   = (const float*)d_in[12];
    const float* W2_last  = (const float*)d_in[13];
    const float* b2_last  = (const float*)d_in[14];
    float* pe = (float*)d_out;

    void *pX, *pH, *pW, *pStats;
    cudaGetSymbolAddress(&pX, g_X);
    cudaGetSymbolAddress(&pH, g_H);
    cudaGetSymbolAddress(&pW, g_Wbf);
    cudaGetSymbolAddress(&pStats, g_stats);
    float* X  = (float*)pX;
    float* H  = (float*)pH;
    __nv_bfloat16* Wbf = (__nv_bfloat16*)pW;
    float* st = (float*)pStats;

    const int smA128 = (192 * 264) * 2 + 512;                  // 101888
    const int smA16  = (192 * 40) * 2 + 512;                   // 15872
    const int smC128 = (192 * 264) * 2 + 512 + 1024;           // 102912
    const int smC64  = (128 * 264) * 2 + 256 + 1024 + 256;     // 69120

    cudaFuncSetAttribute(gin_A<128>,        cudaFuncAttributeMaxDynamicSharedMemorySize, smA128);
    cudaFuncSetAttribute(gin_A<16>,         cudaFuncAttributeMaxDynamicSharedMemorySize, smA16);
    cudaFuncSetAttribute(gin_C<128, false>, cudaFuncAttributeMaxDynamicSharedMemorySize, smC128);
    cudaFuncSetAttribute(gin_C<64, true>,   cudaFuncAttributeMaxDynamicSharedMemorySize, smC64);

    // Launch order: setup(1), A16(2), C128(3), A128(4) <- ncu captures #4
    gin_setup<<<107, 1024>>>(src, dst, W1_first, W1_rest, W2_mid, W2_last);

    for (int l = 0; l < NLAYER; l++) {
        float* gsum = st + l * 2 * HID;
        float* gsq  = gsum + HID;

        if (l == 0) {
            gin_A<16><<<GRID_MAIN, 256, smA16>>>(
                W, Wbf + OFF_W1F, b1_first, eps, 0, H, gsum, gsq);
        } else {
            gin_A<128><<<GRID_MAIN, 256, smA128>>>(
                X, Wbf + OFF_W1R + (size_t)(l - 1) * SZ_WR,
                b1_rest + (size_t)(l - 1) * HID, eps, l, H, gsum, gsq);
        }

        if (l < NLAYER - 1) {
            gin_C<128, false><<<GRID_MAIN, 256, smC128>>>(
                H, Wbf + OFF_W2M + (size_t)l * SZ_WR, b2_mid + (size_t)l * HID,
                gsum, gsq, bn_gamma + (size_t)l * HID, bn_beta + (size_t)l * HID,
                X, nullptr, nullptr);
        } else {
            gin_C<64, true><<<GRID_MAIN, 256, smC64>>>(
                H, Wbf + OFF_W2L, b2_last,
                gsum, gsq, bn_gamma + (size_t)l * HID, bn_beta + (size_t)l * HID,
                nullptr, mask, pe);
        }
    }
}

// round 12
// speedup vs baseline: 1.6873x; 1.6873x over previous
#include <cuda_runtime.h>
#include <cuda_bf16.h>
#include <cstdint>

#define NSUM 2048
#define NMAX 64
#define MFEAT 16
#define HID 128
#define OUTF 64
#define NEDGE 16384
#define NLAYER 4
#define NROWS_TOTAL (NSUM * NMAX)
#define GRID_MAIN 296

// bf16 weight buffer layout (n-major, stride = 2K+8, [hi K | lo K | pad])
#define SZ_W1F (128 * 40)
#define SZ_WR  (128 * 264)
#define SZ_W2L (64 * 264)
#define OFF_W1F 0
#define OFF_W1R (SZ_W1F)
#define OFF_W2M (OFF_W1R + 3 * SZ_WR)
#define OFF_W2L (OFF_W2M + 3 * SZ_WR)
#define WBF_TOTAL (OFF_W2L + SZ_W2L)

// ---------------------------------------------------------------------------
// Device scratch (static __device__ globals: allocation-free per harness rules)
// ---------------------------------------------------------------------------
__device__ float g_X[(size_t)NSUM * NMAX * HID];
__device__ float g_H[(size_t)NSUM * NMAX * HID];
__device__ __nv_bfloat16 g_Wbf[WBF_TOTAL];
__device__ float g_stats[NLAYER * 2 * HID];
__device__ int   g_off[NSUM + 1];
__device__ int   g_csr[NEDGE];

// ---------------------------------------------------------------------------
// Setup kernel (launch #1): CTA 0 builds CSR (count/scan/fill) + zeroes stats;
// CTAs 1..106 convert weights fp32 -> bf16 hi/lo n-major.
// ---------------------------------------------------------------------------
__global__ void __launch_bounds__(1024)
gin_setup(const int* __restrict__ src, const int* __restrict__ dst,
          const float* __restrict__ W1f, const float* __restrict__ W1r,
          const float* __restrict__ W2m, const float* __restrict__ W2l)
{
    const int t = threadIdx.x;            // 1024 threads
    if (blockIdx.x != 0) {
        int idx = (blockIdx.x - 1) * 1024 + t;   // 106*1024 = 108544 exactly
        float w; int k, n, K; size_t doff; int sa;
        if (idx < 2048) {
            K = 16; k = idx / 128; n = idx % 128;
            w = W1f[idx]; doff = OFF_W1F; sa = 40;
        } else if (idx < 2048 + 3 * 16384) {
            int e = idx - 2048; int l = e / 16384; int r = e % 16384;
            K = 128; k = r / 128; n = r % 128;
            w = W1r[e]; doff = OFF_W1R + (size_t)l * SZ_WR; sa = 264;
        } else if (idx < 2048 + 6 * 16384) {
            int e = idx - 2048 - 3 * 16384; int l = e / 16384; int r = e % 16384;
            K = 128; k = r / 128; n = r % 128;
            w = W2m[e]; doff = OFF_W2M + (size_t)l * SZ_WR; sa = 264;
        } else {
            int e = idx - 2048 - 6 * 16384;
            K = 128; k = e / 64; n = e % 64;
            w = W2l[e]; doff = OFF_W2L; sa = 264;
        }
        __nv_bfloat16 hi = __float2bfloat16(w);
        __nv_bfloat16 lo = __float2bfloat16(w - __bfloat162float(hi));
        g_Wbf[doff + (size_t)n * sa + k]     = hi;
        g_Wbf[doff + (size_t)n * sa + K + k] = lo;
        return;
    }

    // ---- CSR build (single CTA) ----
    __shared__ int s0[NSUM], s1[NSUM], cur[NSUM];
    g_stats[t] = 0.f;                     // 4*2*128 == 1024 exactly
    #pragma unroll
    for (int j = 0; j < 2; j++) { s0[t + j * 1024] = 0; cur[t + j * 1024] = 0; }
    __syncthreads();

    #pragma unroll
    for (int j = 0; j < NEDGE / 1024; j++)
        atomicAdd(&s0[dst[t + j * 1024]], 1);
    __syncthreads();

    int* in = s0; int* out = s1;
    for (int d = 1; d < NSUM; d <<= 1) {
        #pragma unroll
        for (int j = 0; j < 2; j++) {
            int i = t + j * 1024;
            int v = in[i];
            if (i >= d) v += in[i - d];
            out[i] = v;
        }
        __syncthreads();
        int* tmp = in; in = out; out = tmp;
    }
    if (t == 0) g_off[0] = 0;
    #pragma unroll
    for (int j = 0; j < 2; j++) g_off[t + j * 1024 + 1] = in[t + j * 1024];
    __syncthreads();

    #pragma unroll
    for (int j = 0; j < NEDGE / 1024; j++) {
        int e = t + j * 1024;
        int d = dst[e];
        int p = atomicAdd(&cur[d], 1);
        int off = d ? in[d - 1] : 0;
        g_csr[off + p] = src[e];
    }
}

// ---------------------------------------------------------------------------
// MMA helpers
// ---------------------------------------------------------------------------
__device__ __forceinline__ void ldsm4(uint32_t* r, uint32_t a)
{
    asm volatile("ldmatrix.sync.aligned.m8n8.x4.shared.b16 {%0,%1,%2,%3}, [%4];"
                 : "=r"(r[0]), "=r"(r[1]), "=r"(r[2]), "=r"(r[3]) : "r"(a));
}

__device__ __forceinline__ void mma_bf16(float* d, const uint32_t* a, uint32_t b0, uint32_t b1)
{
    asm volatile("mma.sync.aligned.m16n8k16.row.col.f32.bf16.bf16.f32 "
                 "{%0,%1,%2,%3},{%4,%5,%6,%7},{%8,%9},{%0,%1,%2,%3};"
                 : "+f"(d[0]), "+f"(d[1]), "+f"(d[2]), "+f"(d[3])
                 : "r"(a[0]), "r"(a[1]), "r"(a[2]), "r"(a[3]), "r"(b0), "r"(b1));
}

// hi/lo bf16 convert + store of a float4 row-chunk
__device__ __forceinline__ void cvt_store(__nv_bfloat16* dhi, __nv_bfloat16* dlo, float4 v)
{
    __nv_bfloat16 h0 = __float2bfloat16(v.x), h1 = __float2bfloat16(v.y);
    __nv_bfloat16 h2 = __float2bfloat16(v.z), h3 = __float2bfloat16(v.w);
    __nv_bfloat162 a; a.x = h0; a.y = h1;
    __nv_bfloat162 b; b.x = h2; b.y = h3;
    ((__nv_bfloat162*)dhi)[0] = a; ((__nv_bfloat162*)dhi)[1] = b;
    __nv_bfloat162 c, d;
    c.x = __float2bfloat16(v.x - __bfloat162float(h0));
    c.y = __float2bfloat16(v.y - __bfloat162float(h1));
    d.x = __float2bfloat16(v.z - __bfloat162float(h2));
    d.y = __float2bfloat16(v.w - __bfloat162float(h3));
    ((__nv_bfloat162*)dlo)[0] = c; ((__nv_bfloat162*)dlo)[1] = d;
}

// GEMM core: 3 segments (hi*hi + lo*hi + hi*lo), KH/16 ksteps each.
template <int KH, int MT>
__device__ __forceinline__ void gemm_mma(const uint32_t* aBase, const uint32_t* bBase,
                                         int kaSel, int kbSel, float (*acc)[4][4])
{
    #pragma unroll
    for (int seg = 0; seg < 3; seg++) {
        const int aoff = (seg == 1) ? KH : 0;
        const int boff = (seg == 2) ? KH : 0;
        #pragma unroll
        for (int ks = 0; ks < KH / 16; ks++) {
            const int ka = (aoff + ks * 16 + kaSel) * 2;
            const int kb = (boff + ks * 16 + kbSel) * 2;
            uint32_t a[MT][4], b[2][4];
            #pragma unroll
            for (int mi = 0; mi < MT; mi++) ldsm4(a[mi], aBase[mi] + ka);
            #pragma unroll
            for (int p = 0; p < 2; p++) ldsm4(b[p], bBase[p] + kb);
            #pragma unroll
            for (int mi = 0; mi < MT; mi++)
                #pragma unroll
                for (int ni = 0; ni < 4; ni++)
                    mma_bf16(acc[mi][ni], a[mi], b[ni >> 1][(ni & 1) * 2], b[ni >> 1][(ni & 1) * 2 + 1]);
        }
    }
}

// ---------------------------------------------------------------------------
// Kernel A: gather + (1+eps)X + GEMM1 (bf16x3 MMA) + BN stat partials
// H stores use streaming hint (__stcs) so the L2 preferentially retains X.
// ---------------------------------------------------------------------------
template <int KH>
__global__ void __launch_bounds__(256, 2)
gin_A(const float* __restrict__ Xin, const __nv_bfloat16* __restrict__ Wg,
      const float* __restrict__ b1, const float* __restrict__ epsArr, int layer,
      float* __restrict__ Hout, float* __restrict__ gsum, float* __restrict__ gsq)
{
    constexpr int SA  = 2 * KH + 8;
    constexpr int KC4 = KH / 4;
    constexpr int EPT = 64 * KC4 / 256;
    extern __shared__ float smf[];
    __nv_bfloat16* Ws = (__nv_bfloat16*)smf;     // 128*SA
    __nv_bfloat16* As = Ws + 128 * SA;           // 64*SA
    float* sb = (float*)(As + 64 * SA);          // 128

    const int tid  = threadIdx.x;
    const int lane = tid & 31, wid = tid >> 5;
    const int wm = wid & 1, wn = wid >> 1;       // 2 (m) x 4 (n) warps
    const int grp = lane >> 2, tig = lane & 3;
    const int sel = lane >> 3, l7 = lane & 7;
    const float epl = 1.f + epsArr[layer];

    {   // stage weights + bias
        const uint4* s = (const uint4*)Wg;
        uint4* d = (uint4*)Ws;
        for (int i = tid; i < 128 * SA / 8; i += 256) d[i] = s[i];
        if (tid < 128) sb[tid] = b1[tid];
    }

    uint32_t aBase[2], bBase[2];
    {
        uint32_t asb = (uint32_t)__cvta_generic_to_shared(As);
        uint32_t wsb = (uint32_t)__cvta_generic_to_shared(Ws);
        aBase[0] = asb + (uint32_t)((wm * 32 + l7 + (sel & 1) * 8) * SA) * 2;
        aBase[1] = aBase[0] + 16 * SA * 2;
        bBase[0] = wsb + (uint32_t)((wn * 32 + l7 + (sel >> 1) * 8) * SA) * 2;
        bBase[1] = bBase[0] + 16 * SA * 2;
    }
    const int kaSel = (sel >> 1) * 8, kbSel = (sel & 1) * 8;

    float psum[8], psq[8];
    #pragma unroll
    for (int q = 0; q < 8; q++) { psum[q] = 0.f; psq[q] = 0.f; }

    __syncthreads();

    for (int n = blockIdx.x; n < NSUM; n += GRID_MAIN) {
        // ---- gather: Z = (1+eps)X[n] + sum X[src] ----
        float4 r[EPT];
        const float4* xn = (const float4*)(Xin + (size_t)n * 64 * KH);
        #pragma unroll
        for (int j = 0; j < EPT; j++) {
            float4 v = xn[tid + j * 256];
            r[j].x = v.x * epl; r[j].y = v.y * epl; r[j].z = v.z * epl; r[j].w = v.w * epl;
        }
        const int eE = g_off[n + 1];
        for (int e = g_off[n]; e < eE; e++) {
            const float4* xs = (const float4*)(Xin + (size_t)g_csr[e] * 64 * KH);
            #pragma unroll
            for (int j = 0; j < EPT; j++) {
                float4 v = xs[tid + j * 256];
                r[j].x += v.x; r[j].y += v.y; r[j].z += v.z; r[j].w += v.w;
            }
        }
        #pragma unroll
        for (int j = 0; j < EPT; j++) {
            int i = tid + j * 256;
            int row = i / KC4, col = (i % KC4) * 4;
            cvt_store(&As[row * SA + col], &As[row * SA + KH + col], r[j]);
        }
        __syncthreads();

        // ---- GEMM ----
        float acc[2][4][4];
        #pragma unroll
        for (int mi = 0; mi < 2; mi++)
            #pragma unroll
            for (int ni = 0; ni < 4; ni++) {
                int c0 = wn * 32 + ni * 8 + tig * 2;
                acc[mi][ni][0] = sb[c0];     acc[mi][ni][1] = sb[c0 + 1];
                acc[mi][ni][2] = sb[c0];     acc[mi][ni][3] = sb[c0 + 1];
            }
        gemm_mma<KH, 2>(aBase, bBase, kaSel, kbSel, acc);

        // ---- epilogue: H (streaming stores) + BN partials ----
        float* hb = Hout + (size_t)n * 64 * 128;
        #pragma unroll
        for (int mi = 0; mi < 2; mi++) {
            int r0 = wm * 32 + mi * 16 + grp;
            #pragma unroll
            for (int ni = 0; ni < 4; ni++) {
                int c0 = wn * 32 + ni * 8 + tig * 2;
                float2 v0 = make_float2(acc[mi][ni][0], acc[mi][ni][1]);
                float2 v1 = make_float2(acc[mi][ni][2], acc[mi][ni][3]);
                __stcs((float2*)&hb[(size_t)r0 * 128 + c0], v0);
                __stcs((float2*)&hb[(size_t)(r0 + 8) * 128 + c0], v1);
                psum[ni * 2 + 0] += v0.x + v1.x;
                psum[ni * 2 + 1] += v0.y + v1.y;
                psq[ni * 2 + 0]  += v0.x * v0.x + v1.x * v1.x;
                psq[ni * 2 + 1]  += v0.y * v0.y + v1.y * v1.y;
            }
        }
        __syncthreads();
    }

    // ---- CTA-end BN reduction (shuffle, then global atomics) ----
    #pragma unroll
    for (int q = 0; q < 8; q++) {
        float s = psum[q], ss = psq[q];
        s  += __shfl_xor_sync(0xffffffffu, s, 4);
        s  += __shfl_xor_sync(0xffffffffu, s, 8);
        s  += __shfl_xor_sync(0xffffffffu, s, 16);
        ss += __shfl_xor_sync(0xffffffffu, ss, 4);
        ss += __shfl_xor_sync(0xffffffffu, ss, 8);
        ss += __shfl_xor_sync(0xffffffffu, ss, 16);
        if (lane < 4) {
            int c = wn * 32 + (q >> 1) * 8 + lane * 2 + (q & 1);
            atomicAdd(&gsum[c], s);
            atomicAdd(&gsq[c], ss);
        }
    }
}

// ---------------------------------------------------------------------------
// Kernel C: BN(params in-CTA) + ReLU + GEMM2; LAST fuses masked PE reduction
// H reads use streaming hint (__ldcs): last use, keep X resident instead.
// ---------------------------------------------------------------------------
template <int NOUT, bool LAST>
__global__ void __launch_bounds__(256, 2)
gin_C(const float* __restrict__ Hin, const __nv_bfloat16* __restrict__ Wg,
      const float* __restrict__ b2,
      const float* __restrict__ gsum, const float* __restrict__ gsq,
      const float* __restrict__ gamma, const float* __restrict__ beta,
      float* __restrict__ Xout, const float* __restrict__ mask, float* __restrict__ pe)
{
    constexpr int KH = 128, SA = 264;
    constexpr int WGM = (NOUT == 128) ? 2 : 4;
    constexpr int MT  = (NOUT == 128) ? 2 : 1;
    extern __shared__ float smf[];
    __nv_bfloat16* Ws = (__nv_bfloat16*)smf;     // NOUT*SA
    __nv_bfloat16* As = Ws + NOUT * SA;          // 64*SA
    float* sb  = (float*)(As + 64 * SA);         // NOUT
    float* ssc = sb + NOUT;                      // 128
    float* ssh = ssc + 128;                      // 128
    float* spe = ssh + 128;                      // 64 (LAST only)

    const int tid  = threadIdx.x;
    const int lane = tid & 31, wid = tid >> 5;
    const int wm = wid % WGM, wn = wid / WGM;
    const int grp = lane >> 2, tig = lane & 3;
    const int sel = lane >> 3, l7 = lane & 7;
    const int rowbase = wm * MT * 16, colbase = wn * 32;

    {
        const uint4* s = (const uint4*)Wg;
        uint4* d = (uint4*)Ws;
        for (int i = tid; i < NOUT * SA / 8; i += 256) d[i] = s[i];
        if (tid < NOUT) sb[tid] = b2[tid];
        if (tid < 128) {
            // BN finalize in-CTA
            const float inv = 1.f / (float)NROWS_TOTAL;
            float mu  = gsum[tid] * inv;
            float var = gsq[tid] * inv - mu * mu;
            float rs  = rsqrtf(var + 1e-5f);
            float scl = rs * gamma[tid];
            ssc[tid] = scl;
            ssh[tid] = beta[tid] - mu * scl;
        }
    }

    uint32_t aBase[MT], bBase[2];
    {
        uint32_t asb = (uint32_t)__cvta_generic_to_shared(As);
        uint32_t wsb = (uint32_t)__cvta_generic_to_shared(Ws);
        #pragma unroll
        for (int mi = 0; mi < MT; mi++)
            aBase[mi] = asb + (uint32_t)((rowbase + mi * 16 + l7 + (sel & 1) * 8) * SA) * 2;
        bBase[0] = wsb + (uint32_t)((colbase + l7 + (sel >> 1) * 8) * SA) * 2;
        bBase[1] = bBase[0] + 16 * SA * 2;
    }
    const int kaSel = (sel >> 1) * 8, kbSel = (sel & 1) * 8;

    __syncthreads();

    for (int n = blockIdx.x; n < NSUM; n += GRID_MAIN) {
        // ---- BN + ReLU + hi/lo convert into A (streaming H reads) ----
        const float4* h4 = (const float4*)(Hin + (size_t)n * 64 * 128);
        #pragma unroll
        for (int j = 0; j < 8; j++) {
            int i = tid + j * 256;
            int row = i >> 5, col = (i & 31) * 4;
            float4 h = __ldcs(&h4[i]);
            float4 sc = *(const float4*)&ssc[col];
            float4 sh = *(const float4*)&ssh[col];
            float4 a;
            a.x = fmaxf(fmaf(h.x, sc.x, sh.x), 0.f);
            a.y = fmaxf(fmaf(h.y, sc.y, sh.y), 0.f);
            a.z = fmaxf(fmaf(h.z, sc.z, sh.z), 0.f);
            a.w = fmaxf(fmaf(h.w, sc.w, sh.w), 0.f);
            cvt_store(&As[row * SA + col], &As[row * SA + KH + col], a);
        }
        __syncthreads();

        // ---- GEMM ----
        float acc[MT][4][4];
        #pragma unroll
        for (int mi = 0; mi < MT; mi++)
            #pragma unroll
            for (int ni = 0; ni < 4; ni++) {
                int c0 = colbase + ni * 8 + tig * 2;
                acc[mi][ni][0] = sb[c0];     acc[mi][ni][1] = sb[c0 + 1];
                acc[mi][ni][2] = sb[c0];     acc[mi][ni][3] = sb[c0 + 1];
            }
        gemm_mma<KH, MT>(aBase, bBase, kaSel, kbSel, acc);

        if (!LAST) {
            float* xb = Xout + (size_t)n * 64 * 128;
            #pragma unroll
            for (int mi = 0; mi < MT; mi++) {
                int r0 = rowbase + mi * 16 + grp;
                #pragma unroll
                for (int ni = 0; ni < 4; ni++) {
                    int c0 = colbase + ni * 8 + tig * 2;
                    *(float2*)&xb[(size_t)r0 * 128 + c0]       = make_float2(acc[mi][ni][0], acc[mi][ni][1]);
                    *(float2*)&xb[(size_t)(r0 + 8) * 128 + c0] = make_float2(acc[mi][ni][2], acc[mi][ni][3]);
                }
            }
        } else {
            if (tid < 64) spe[tid] = 0.f;
            __syncthreads();
            float m0 = mask[(size_t)n * 64 + rowbase + grp];
            float m1 = mask[(size_t)n * 64 + rowbase + grp + 8];
            #pragma unroll
            for (int ni = 0; ni < 4; ni++) {
                float p0 = m0 * acc[0][ni][0] + m1 * acc[0][ni][2];
                float p1 = m0 * acc[0][ni][1] + m1 * acc[0][ni][3];
                p0 += __shfl_xor_sync(0xffffffffu, p0, 4);
                p0 += __shfl_xor_sync(0xffffffffu, p0, 8);
                p0 += __shfl_xor_sync(0xffffffffu, p0, 16);
                p1 += __shfl_xor_sync(0xffffffffu, p1, 4);
                p1 += __shfl_xor_sync(0xffffffffu, p1, 8);
                p1 += __shfl_xor_sync(0xffffffffu, p1, 16);
                if (lane < 4) {
                    int c = colbase + ni * 8 + lane * 2;
                    atomicAdd(&spe[c], p0);
                    atomicAdd(&spe[c + 1], p1);
                }
            }
            __syncthreads();
            if (tid < 64) pe[(size_t)n * 64 + tid] = spe[tid];
        }
        __syncthreads();
    }
}

// ---------------------------------------------------------------------------
// Host-side launch
// ---------------------------------------------------------------------------
extern "C" void kernel_launch(void* const* d_in, const int* in_sizes, int n_in,
                              void* d_out, int out_size)
{
    const float* W        = (const float*)d_in[0];
    const float* mask     = (const float*)d_in[1];
    const int*   src      = (const int*)d_in[2];
    const int*   dst      = (const int*)d_in[3];
    const float* eps      = (const float*)d_in[4];
    const float* W1_first = (const float*)d_in[5];
    const float* b1_first = (const float*)d_in[6];
    const float* W1_rest  = (const float*)d_in[7];
    const float* b1_rest  = (const float*)d_in[8];
    const float* bn_gamma = (const float*)d_in[9];
    const float* bn_beta  = (const float*)d_in[10];
    const float* W2_mid   = (const float*)d_in[11];
    const float* b2_mid   = (const float*)d_in[12];
    const float* W2_last  = (const float*)d_in[13];
    const float* b2_last  = (const float*)d_in[14];
    float* pe = (float*)d_out;

    void *pX, *pH, *pW, *pStats;
    cudaGetSymbolAddress(&pX, g_X);
    cudaGetSymbolAddress(&pH, g_H);
    cudaGetSymbolAddress(&pW, g_Wbf);
    cudaGetSymbolAddress(&pStats, g_stats);
    float* X  = (float*)pX;
    float* H  = (float*)pH;
    __nv_bfloat16* Wbf = (__nv_bfloat16*)pW;
    float* st = (float*)pStats;

    const int smA128 = (192 * 264) * 2 + 512;                  // 101888
    const int smA16  = (192 * 40) * 2 + 512;                   // 15872
    const int smC128 = (192 * 264) * 2 + 512 + 1024;           // 102912
    const int smC64  = (128 * 264) * 2 + 256 + 1024 + 256;     // 69120

    cudaFuncSetAttribute(gin_A<128>,        cudaFuncAttributeMaxDynamicSharedMemorySize, smA128);
    cudaFuncSetAttribute(gin_A<16>,         cudaFuncAttributeMaxDynamicSharedMemorySize, smA16);
    cudaFuncSetAttribute(gin_C<128, false>, cudaFuncAttributeMaxDynamicSharedMemorySize, smC128);
    cudaFuncSetAttribute(gin_C<64, true>,   cudaFuncAttributeMaxDynamicSharedMemorySize, smC64);

    // Launch order: setup(1), A16(2), C128(3), A128(4) <- ncu captures #4
    gin_setup<<<107, 1024>>>(src, dst, W1_first, W1_rest, W2_mid, W2_last);

    for (int l = 0; l < NLAYER; l++) {
        float* gsum = st + l * 2 * HID;
        float* gsq  = gsum + HID;

        if (l == 0) {
            gin_A<16><<<GRID_MAIN, 256, smA16>>>(
                W, Wbf + OFF_W1F, b1_first, eps, 0, H, gsum, gsq);
        } else {
            gin_A<128><<<GRID_MAIN, 256, smA128>>>(
                X, Wbf + OFF_W1R + (size_t)(l - 1) * SZ_WR,
                b1_rest + (size_t)(l - 1) * HID, eps, l, H, gsum, gsq);
        }

        if (l < NLAYER - 1) {
            gin_C<128, false><<<GRID_MAIN, 256, smC128>>>(
                H, Wbf + OFF_W2M + (size_t)l * SZ_WR, b2_mid + (size_t)l * HID,
                gsum, gsq, bn_gamma + (size_t)l * HID, bn_beta + (size_t)l * HID,
                X, nullptr, nullptr);
        } else {
            gin_C<64, true><<<GRID_MAIN, 256, smC64>>>(
                H, Wbf + OFF_W2L, b2_last,
                gsum, gsq, bn_gamma + (size_t)l * HID, bn_beta + (size_t)l * HID,
                nullptr, mask, pe);
        }
    }
}

// round 13
// speedup vs baseline: 2.4170x; 1.4325x over previous
#include <cuda_runtime.h>
#include <cuda_bf16.h>
#include <cstdint>

#define NSUM 2048
#define NMAX 64
#define MFEAT 16
#define HID 128
#define OUTF 64
#define NEDGE 16384
#define NROWS_TOTAL (NSUM * NMAX)
#define GRID_MAIN 296

// bf16 weight buffer: W1_first (K=16) + 3 combined C_l = W2_mid[l]@W1_rest[l] (K=128)
// n-major, stride = 2K+8, [hi K | lo K | pad]
#define SZ_W1F (128 * 40)
#define SZ_WR  (128 * 264)
#define OFF_W1F 0
#define OFF_C(l) (SZ_W1F + (l) * SZ_WR)
#define WBF_TOTAL (SZ_W1F + 3 * SZ_WR)

// ---------------------------------------------------------------------------
// Device scratch
// ---------------------------------------------------------------------------
__device__ float g_Ha[(size_t)NSUM * NMAX * HID];
__device__ float g_Hb[(size_t)NSUM * NMAX * HID];
__device__ __nv_bfloat16 g_Wbf[WBF_TOTAL];
__device__ float g_Cf[3 * 16384 + 3 * 128];   // fp32 combined weights + b2@W1 vectors
__device__ float g_stats[4 * 2 * HID];
__device__ int   g_off[NSUM + 1];
__device__ int   g_csr[NEDGE];

// ---------------------------------------------------------------------------
// Setup1: CTA0 builds CSR + zeroes stats; CTAs 1..48 compute C_l = W2@W1 (fp32);
// CTA 49 computes bw_l = b2@W1.
// ---------------------------------------------------------------------------
__global__ void __launch_bounds__(1024)
gin_setup1(const int* __restrict__ src, const int* __restrict__ dst,
           const float* __restrict__ W1r, const float* __restrict__ W2m,
           const float* __restrict__ b2m)
{
    const int t = threadIdx.x;
    const int b = blockIdx.x;

    if (b >= 1 && b <= 48) {
        int idx = (b - 1) * 1024 + t;          // 0..49151
        int l = idx / 16384, r = idx % 16384;
        int k = r / 128, j = r % 128;
        const float* w2 = W2m + l * 16384 + k * 128;
        const float* w1 = W1r + l * 16384 + j;
        float s0 = 0.f, s1 = 0.f, s2 = 0.f, s3 = 0.f;
        #pragma unroll 8
        for (int m = 0; m < 128; m += 4) {
            s0 += w2[m]     * w1[(size_t)m * 128];
            s1 += w2[m + 1] * w1[(size_t)(m + 1) * 128];
            s2 += w2[m + 2] * w1[(size_t)(m + 2) * 128];
            s3 += w2[m + 3] * w1[(size_t)(m + 3) * 128];
        }
        g_Cf[idx] = (s0 + s1) + (s2 + s3);
        return;
    }
    if (b == 49) {
        if (t < 384) {
            int l = t / 128, j = t % 128;
            const float* bb = b2m + l * 128;
            const float* w1 = W1r + l * 16384 + j;
            float s = 0.f;
            #pragma unroll 8
            for (int m = 0; m < 128; m++) s += bb[m] * w1[(size_t)m * 128];
            g_Cf[3 * 16384 + t] = s;
        }
        return;
    }

    // ---- CTA 0: CSR build + zero stats ----
    __shared__ int s0[NSUM], s1[NSUM], cur[NSUM];
    g_stats[t] = 0.f;                     // 4*2*128 == 1024 exactly
    #pragma unroll
    for (int j = 0; j < 2; j++) { s0[t + j * 1024] = 0; cur[t + j * 1024] = 0; }
    __syncthreads();

    #pragma unroll
    for (int j = 0; j < NEDGE / 1024; j++)
        atomicAdd(&s0[dst[t + j * 1024]], 1);
    __syncthreads();

    int* in = s0; int* out = s1;
    for (int d = 1; d < NSUM; d <<= 1) {
        #pragma unroll
        for (int j = 0; j < 2; j++) {
            int i = t + j * 1024;
            int v = in[i];
            if (i >= d) v += in[i - d];
            out[i] = v;
        }
        __syncthreads();
        int* tmp = in; in = out; out = tmp;
    }
    if (t == 0) g_off[0] = 0;
    #pragma unroll
    for (int j = 0; j < 2; j++) g_off[t + j * 1024 + 1] = in[t + j * 1024];
    __syncthreads();

    #pragma unroll
    for (int j = 0; j < NEDGE / 1024; j++) {
        int e = t + j * 1024;
        int d = dst[e];
        int p = atomicAdd(&cur[d], 1);
        int off = d ? in[d - 1] : 0;
        g_csr[off + p] = src[e];
    }
}

// ---------------------------------------------------------------------------
// Setup2: convert W1_first + the three fp32 C matrices to bf16 hi/lo n-major.
// 2048 + 49152 = 51200 = 50 CTAs x 1024 exactly.
// ---------------------------------------------------------------------------
__global__ void __launch_bounds__(1024)
gin_setup2(const float* __restrict__ W1f)
{
    int idx = blockIdx.x * 1024 + threadIdx.x;
    float w; int k, n, K; size_t doff; int sa;
    if (idx < 2048) {
        K = 16; k = idx / 128; n = idx % 128;
        w = W1f[idx]; doff = OFF_W1F; sa = 40;
    } else {
        int e = idx - 2048; int l = e / 16384; int r = e % 16384;
        K = 128; k = r / 128; n = r % 128;
        w = g_Cf[e]; doff = OFF_C(l); sa = 264;
    }
    __nv_bfloat16 hi = __float2bfloat16(w);
    __nv_bfloat16 lo = __float2bfloat16(w - __bfloat162float(hi));
    g_Wbf[doff + (size_t)n * sa + k]     = hi;
    g_Wbf[doff + (size_t)n * sa + K + k] = lo;
}

// ---------------------------------------------------------------------------
// MMA helpers
// ---------------------------------------------------------------------------
__device__ __forceinline__ void ldsm4(uint32_t* r, uint32_t a)
{
    asm volatile("ldmatrix.sync.aligned.m8n8.x4.shared.b16 {%0,%1,%2,%3}, [%4];"
                 : "=r"(r[0]), "=r"(r[1]), "=r"(r[2]), "=r"(r[3]) : "r"(a));
}

__device__ __forceinline__ void mma_bf16(float* d, const uint32_t* a, uint32_t b0, uint32_t b1)
{
    asm volatile("mma.sync.aligned.m16n8k16.row.col.f32.bf16.bf16.f32 "
                 "{%0,%1,%2,%3},{%4,%5,%6,%7},{%8,%9},{%0,%1,%2,%3};"
                 : "+f"(d[0]), "+f"(d[1]), "+f"(d[2]), "+f"(d[3])
                 : "r"(a[0]), "r"(a[1]), "r"(a[2]), "r"(a[3]), "r"(b0), "r"(b1));
}

// hi/lo bf16 convert + store of a float4 row-chunk
__device__ __forceinline__ void cvt_store(__nv_bfloat16* dhi, __nv_bfloat16* dlo, float4 v)
{
    __nv_bfloat16 h0 = __float2bfloat16(v.x), h1 = __float2bfloat16(v.y);
    __nv_bfloat16 h2 = __float2bfloat16(v.z), h3 = __float2bfloat16(v.w);
    __nv_bfloat162 a; a.x = h0; a.y = h1;
    __nv_bfloat162 b; b.x = h2; b.y = h3;
    ((__nv_bfloat162*)dhi)[0] = a; ((__nv_bfloat162*)dhi)[1] = b;
    __nv_bfloat162 c, d;
    c.x = __float2bfloat16(v.x - __bfloat162float(h0));
    c.y = __float2bfloat16(v.y - __bfloat162float(h1));
    d.x = __float2bfloat16(v.z - __bfloat162float(h2));
    d.y = __float2bfloat16(v.w - __bfloat162float(h3));
    ((__nv_bfloat162*)dlo)[0] = c; ((__nv_bfloat162*)dlo)[1] = d;
}

// GEMM core: 3 segments (hi*hi + lo*hi + hi*lo), KH/16 ksteps each.
template <int KH, int MT>
__device__ __forceinline__ void gemm_mma(const uint32_t* aBase, const uint32_t* bBase,
                                         int kaSel, int kbSel, float (*acc)[4][4])
{
    #pragma unroll
    for (int seg = 0; seg < 3; seg++) {
        const int aoff = (seg == 1) ? KH : 0;
        const int boff = (seg == 2) ? KH : 0;
        #pragma unroll
        for (int ks = 0; ks < KH / 16; ks++) {
            const int ka = (aoff + ks * 16 + kaSel) * 2;
            const int kb = (boff + ks * 16 + kbSel) * 2;
            uint32_t a[MT][4], b[2][4];
            #pragma unroll
            for (int mi = 0; mi < MT; mi++) ldsm4(a[mi], aBase[mi] + ka);
            #pragma unroll
            for (int p = 0; p < 2; p++) ldsm4(b[p], bBase[p] + kb);
            #pragma unroll
            for (int mi = 0; mi < MT; mi++)
                #pragma unroll
                for (int ni = 0; ni < 4; ni++)
                    mma_bf16(acc[mi][ni], a[mi], b[ni >> 1][(ni & 1) * 2], b[ni >> 1][(ni & 1) * 2 + 1]);
        }
    }
}

// ---------------------------------------------------------------------------
// Kernel A (layer 0 only): gather raw input W + GEMM1(16->128) + stats
// ---------------------------------------------------------------------------
__global__ void __launch_bounds__(256, 2)
gin_A16(const float* __restrict__ Xin, const __nv_bfloat16* __restrict__ Wg,
        const float* __restrict__ b1, const float* __restrict__ epsArr,
        float* __restrict__ Hout, float* __restrict__ gsum, float* __restrict__ gsq)
{
    constexpr int KH = 16, SA = 40, KC4 = 4, EPT = 1;
    extern __shared__ float smf[];
    __nv_bfloat16* Ws = (__nv_bfloat16*)smf;     // 128*40
    __nv_bfloat16* As = Ws + 128 * SA;           // 64*40
    float* sb = (float*)(As + 64 * SA);          // 128

    const int tid  = threadIdx.x;
    const int lane = tid & 31, wid = tid >> 5;
    const int wm = wid & 1, wn = wid >> 1;
    const int grp = lane >> 2, tig = lane & 3;
    const int sel = lane >> 3, l7 = lane & 7;
    const float epl = 1.f + epsArr[0];

    {
        const uint4* s = (const uint4*)Wg;
        uint4* d = (uint4*)Ws;
        for (int i = tid; i < 128 * SA / 8; i += 256) d[i] = s[i];
        if (tid < 128) sb[tid] = b1[tid];
    }

    uint32_t aBase[2], bBase[2];
    {
        uint32_t asb = (uint32_t)__cvta_generic_to_shared(As);
        uint32_t wsb = (uint32_t)__cvta_generic_to_shared(Ws);
        aBase[0] = asb + (uint32_t)((wm * 32 + l7 + (sel & 1) * 8) * SA) * 2;
        aBase[1] = aBase[0] + 16 * SA * 2;
        bBase[0] = wsb + (uint32_t)((wn * 32 + l7 + (sel >> 1) * 8) * SA) * 2;
        bBase[1] = bBase[0] + 16 * SA * 2;
    }
    const int kaSel = (sel >> 1) * 8, kbSel = (sel & 1) * 8;

    float psum[8], psq[8];
    #pragma unroll
    for (int q = 0; q < 8; q++) { psum[q] = 0.f; psq[q] = 0.f; }

    __syncthreads();

    for (int n = blockIdx.x; n < NSUM; n += GRID_MAIN) {
        float4 r[EPT];
        const float4* xn = (const float4*)(Xin + (size_t)n * 64 * KH);
        #pragma unroll
        for (int j = 0; j < EPT; j++) {
            float4 v = xn[tid + j * 256];
            r[j].x = v.x * epl; r[j].y = v.y * epl; r[j].z = v.z * epl; r[j].w = v.w * epl;
        }
        const int eE = g_off[n + 1];
        for (int e = g_off[n]; e < eE; e++) {
            const float4* xs = (const float4*)(Xin + (size_t)g_csr[e] * 64 * KH);
            #pragma unroll
            for (int j = 0; j < EPT; j++) {
                float4 v = xs[tid + j * 256];
                r[j].x += v.x; r[j].y += v.y; r[j].z += v.z; r[j].w += v.w;
            }
        }
        #pragma unroll
        for (int j = 0; j < EPT; j++) {
            int i = tid + j * 256;
            int row = i / KC4, col = (i % KC4) * 4;
            cvt_store(&As[row * SA + col], &As[row * SA + KH + col], r[j]);
        }
        __syncthreads();

        float acc[2][4][4];
        #pragma unroll
        for (int mi = 0; mi < 2; mi++)
            #pragma unroll
            for (int ni = 0; ni < 4; ni++) {
                int c0 = wn * 32 + ni * 8 + tig * 2;
                acc[mi][ni][0] = sb[c0];     acc[mi][ni][1] = sb[c0 + 1];
                acc[mi][ni][2] = sb[c0];     acc[mi][ni][3] = sb[c0 + 1];
            }
        gemm_mma<KH, 2>(aBase, bBase, kaSel, kbSel, acc);

        float* hb = Hout + (size_t)n * 64 * 128;
        #pragma unroll
        for (int mi = 0; mi < 2; mi++) {
            int r0 = wm * 32 + mi * 16 + grp;
            #pragma unroll
            for (int ni = 0; ni < 4; ni++) {
                int c0 = wn * 32 + ni * 8 + tig * 2;
                float2 v0 = make_float2(acc[mi][ni][0], acc[mi][ni][1]);
                float2 v1 = make_float2(acc[mi][ni][2], acc[mi][ni][3]);
                *(float2*)&hb[(size_t)r0 * 128 + c0]       = v0;
                *(float2*)&hb[(size_t)(r0 + 8) * 128 + c0] = v1;
                psum[ni * 2 + 0] += v0.x + v1.x;
                psum[ni * 2 + 1] += v0.y + v1.y;
                psq[ni * 2 + 0]  += v0.x * v0.x + v1.x * v1.x;
                psq[ni * 2 + 1]  += v0.y * v0.y + v1.y * v1.y;
            }
        }
        __syncthreads();
    }

    #pragma unroll
    for (int q = 0; q < 8; q++) {
        float s = psum[q], ss = psq[q];
        s  += __shfl_xor_sync(0xffffffffu, s, 4);
        s  += __shfl_xor_sync(0xffffffffu, s, 8);
        s  += __shfl_xor_sync(0xffffffffu, s, 16);
        ss += __shfl_xor_sync(0xffffffffu, ss, 4);
        ss += __shfl_xor_sync(0xffffffffu, ss, 8);
        ss += __shfl_xor_sync(0xffffffffu, ss, 16);
        if (lane < 4) {
            int c = wn * 32 + (q >> 1) * 8 + lane * 2 + (q & 1);
            atomicAdd(&gsum[c], s);
            atomicAdd(&gsq[c], ss);
        }
    }
}

// ---------------------------------------------------------------------------
// Kernel G (middle layers): gather with INLINE relu(BN(.)) on H_l, then ONE
// combined GEMM H_{l+1} = U@(W2@W1) + (1+eps+deg)*(b2@W1) + b1, + stats.
// ---------------------------------------------------------------------------
__global__ void __launch_bounds__(256, 2)
gin_G(const float* __restrict__ Hin, const __nv_bfloat16* __restrict__ Wg,
      const float* __restrict__ statsIn, const float* __restrict__ gamma,
      const float* __restrict__ beta, const float* __restrict__ epsArr, int epsIdx,
      const float* __restrict__ b1v, const float* __restrict__ bwv,
      float* __restrict__ Hout, float* __restrict__ gsum, float* __restrict__ gsq)
{
    constexpr int KH = 128, SA = 264;
    extern __shared__ float smf[];
    __nv_bfloat16* Ws = (__nv_bfloat16*)smf;     // 128*264
    __nv_bfloat16* As = Ws + 128 * SA;           // 64*264
    float* sb1 = (float*)(As + 64 * SA);         // 128
    float* sbw = sb1 + 128;                      // 128
    float* ssc = sbw + 128;                      // 128
    float* ssh = ssc + 128;                      // 128

    const int tid  = threadIdx.x;
    const int lane = tid & 31, wid = tid >> 5;
    const int wm = wid & 1, wn = wid >> 1;
    const int grp = lane >> 2, tig = lane & 3;
    const int sel = lane >> 3, l7 = lane & 7;
    const float epl = 1.f + epsArr[epsIdx];

    {
        const uint4* s = (const uint4*)Wg;
        uint4* d = (uint4*)Ws;
        for (int i = tid; i < 128 * SA / 8; i += 256) d[i] = s[i];
        if (tid < 128) {
            sb1[tid] = b1v[tid];
            sbw[tid] = bwv[tid];
            const float inv = 1.f / (float)NROWS_TOTAL;
            float mu  = statsIn[tid] * inv;
            float var = statsIn[128 + tid] * inv - mu * mu;
            float rs  = rsqrtf(var + 1e-5f);
            float scl = rs * gamma[tid];
            ssc[tid] = scl;
            ssh[tid] = beta[tid] - mu * scl;
        }
    }

    uint32_t aBase[2], bBase[2];
    {
        uint32_t asb = (uint32_t)__cvta_generic_to_shared(As);
        uint32_t wsb = (uint32_t)__cvta_generic_to_shared(Ws);
        aBase[0] = asb + (uint32_t)((wm * 32 + l7 + (sel & 1) * 8) * SA) * 2;
        aBase[1] = aBase[0] + 16 * SA * 2;
        bBase[0] = wsb + (uint32_t)((wn * 32 + l7 + (sel >> 1) * 8) * SA) * 2;
        bBase[1] = bBase[0] + 16 * SA * 2;
    }
    const int kaSel = (sel >> 1) * 8, kbSel = (sel & 1) * 8;

    float psum[8], psq[8];
    #pragma unroll
    for (int q = 0; q < 8; q++) { psum[q] = 0.f; psq[q] = 0.f; }

    __syncthreads();

    // per-thread fixed feature columns (i % 32 == tid % 32 since 256 % 32 == 0)
    const int myc = (tid & 31) * 4;
    const float4 sc4 = *(const float4*)&ssc[myc];
    const float4 sh4 = *(const float4*)&ssh[myc];

    for (int n = blockIdx.x; n < NSUM; n += GRID_MAIN) {
        const int eB = g_off[n], eE = g_off[n + 1];
        const float fac = epl + (float)(eE - eB);

        // ---- gather with inline relu(BN(h)) ----
        float4 r[8];
        const float4* xn = (const float4*)(Hin + (size_t)n * 8192);
        #pragma unroll
        for (int j = 0; j < 8; j++) {
            float4 v = xn[tid + j * 256];
            r[j].x = fmaxf(fmaf(v.x, sc4.x, sh4.x), 0.f) * epl;
            r[j].y = fmaxf(fmaf(v.y, sc4.y, sh4.y), 0.f) * epl;
            r[j].z = fmaxf(fmaf(v.z, sc4.z, sh4.z), 0.f) * epl;
            r[j].w = fmaxf(fmaf(v.w, sc4.w, sh4.w), 0.f) * epl;
        }
        for (int e = eB; e < eE; e++) {
            const float4* xs = (const float4*)(Hin + (size_t)g_csr[e] * 8192);
            #pragma unroll
            for (int j = 0; j < 8; j++) {
                float4 v = xs[tid + j * 256];
                r[j].x += fmaxf(fmaf(v.x, sc4.x, sh4.x), 0.f);
                r[j].y += fmaxf(fmaf(v.y, sc4.y, sh4.y), 0.f);
                r[j].z += fmaxf(fmaf(v.z, sc4.z, sh4.z), 0.f);
                r[j].w += fmaxf(fmaf(v.w, sc4.w, sh4.w), 0.f);
            }
        }
        #pragma unroll
        for (int j = 0; j < 8; j++) {
            int i = tid + j * 256;
            int row = i >> 5;
            cvt_store(&As[row * SA + myc], &As[row * SA + KH + myc], r[j]);
        }
        __syncthreads();

        // ---- combined GEMM, bias = b1 + fac*(b2@W1) ----
        float acc[2][4][4];
        #pragma unroll
        for (int mi = 0; mi < 2; mi++)
            #pragma unroll
            for (int ni = 0; ni < 4; ni++) {
                int c0 = wn * 32 + ni * 8 + tig * 2;
                float bA = fmaf(fac, sbw[c0],     sb1[c0]);
                float bB = fmaf(fac, sbw[c0 + 1], sb1[c0 + 1]);
                acc[mi][ni][0] = bA; acc[mi][ni][1] = bB;
                acc[mi][ni][2] = bA; acc[mi][ni][3] = bB;
            }
        gemm_mma<KH, 2>(aBase, bBase, kaSel, kbSel, acc);

        // ---- epilogue: H_next + stats ----
        float* hb = Hout + (size_t)n * 8192;
        #pragma unroll
        for (int mi = 0; mi < 2; mi++) {
            int r0 = wm * 32 + mi * 16 + grp;
            #pragma unroll
            for (int ni = 0; ni < 4; ni++) {
                int c0 = wn * 32 + ni * 8 + tig * 2;
                float2 v0 = make_float2(acc[mi][ni][0], acc[mi][ni][1]);
                float2 v1 = make_float2(acc[mi][ni][2], acc[mi][ni][3]);
                *(float2*)&hb[(size_t)r0 * 128 + c0]       = v0;
                *(float2*)&hb[(size_t)(r0 + 8) * 128 + c0] = v1;
                psum[ni * 2 + 0] += v0.x + v1.x;
                psum[ni * 2 + 1] += v0.y + v1.y;
                psq[ni * 2 + 0]  += v0.x * v0.x + v1.x * v1.x;
                psq[ni * 2 + 1]  += v0.y * v0.y + v1.y * v1.y;
            }
        }
        __syncthreads();
    }

    #pragma unroll
    for (int q = 0; q < 8; q++) {
        float s = psum[q], ss = psq[q];
        s  += __shfl_xor_sync(0xffffffffu, s, 4);
        s  += __shfl_xor_sync(0xffffffffu, s, 8);
        s  += __shfl_xor_sync(0xffffffffu, s, 16);
        ss += __shfl_xor_sync(0xffffffffu, ss, 4);
        ss += __shfl_xor_sync(0xffffffffu, ss, 8);
        ss += __shfl_xor_sync(0xffffffffu, ss, 16);
        if (lane < 4) {
            int c = wn * 32 + (q >> 1) * 8 + lane * 2 + (q & 1);
            atomicAdd(&gsum[c], s);
            atomicAdd(&gsq[c], ss);
        }
    }
}

// ---------------------------------------------------------------------------
// Kernel KL (last layer): PE[n] = (Σ_r mask*relu(bn(H4)))@W2_last + (Σmask)*b2
// One graph per 128-thread CTA; fp32 matvec (tiny: 64x smaller than full GEMM).
// ---------------------------------------------------------------------------
__global__ void __launch_bounds__(128)
gin_KL(const float* __restrict__ H4, const float* __restrict__ statsIn,
       const float* __restrict__ gamma, const float* __restrict__ beta,
       const float* __restrict__ mask, const float* __restrict__ W2L,
       const float* __restrict__ b2L, float* __restrict__ pe)
{
    __shared__ float v[128];
    __shared__ float smt;
    const int n = blockIdx.x;
    const int c = threadIdx.x;

    const float inv = 1.f / (float)NROWS_TOTAL;
    float mu  = statsIn[c] * inv;
    float var = statsIn[128 + c] * inv - mu * mu;
    float rs  = rsqrtf(var + 1e-5f);
    float sc  = rs * gamma[c];
    float sh  = beta[c] - mu * sc;

    const float* hb = H4 + (size_t)n * 8192 + c;
    const float* mb = mask + (size_t)n * 64;
    float a0 = 0.f, a1 = 0.f, a2 = 0.f, a3 = 0.f, mt = 0.f;
    #pragma unroll 4
    for (int r = 0; r < 64; r += 4) {
        float mA = mb[r], mB = mb[r + 1], mC = mb[r + 2], mD = mb[r + 3];
        a0 += mA * fmaxf(fmaf(hb[(size_t)r * 128],       sc, sh), 0.f);
        a1 += mB * fmaxf(fmaf(hb[(size_t)(r + 1) * 128], sc, sh), 0.f);
        a2 += mC * fmaxf(fmaf(hb[(size_t)(r + 2) * 128], sc, sh), 0.f);
        a3 += mD * fmaxf(fmaf(hb[(size_t)(r + 3) * 128], sc, sh), 0.f);
        mt += mA + mB + mC + mD;
    }
    v[c] = (a0 + a1) + (a2 + a3);
    if (c == 0) smt = mt;
    __syncthreads();

    if (c < OUTF) {
        float acc0 = smt * b2L[c], acc1 = 0.f, acc2 = 0.f, acc3 = 0.f;
        #pragma unroll 8
        for (int k = 0; k < 128; k += 4) {
            acc0 += v[k]     * W2L[(size_t)k * 64 + c];
            acc1 += v[k + 1] * W2L[(size_t)(k + 1) * 64 + c];
            acc2 += v[k + 2] * W2L[(size_t)(k + 2) * 64 + c];
            acc3 += v[k + 3] * W2L[(size_t)(k + 3) * 64 + c];
        }
        pe[(size_t)n * 64 + c] = (acc0 + acc1) + (acc2 + acc3);
    }
}

// ---------------------------------------------------------------------------
// Host-side launch
// ---------------------------------------------------------------------------
extern "C" void kernel_launch(void* const* d_in, const int* in_sizes, int n_in,
                              void* d_out, int out_size)
{
    const float* W        = (const float*)d_in[0];
    const float* mask     = (const float*)d_in[1];
    const int*   src      = (const int*)d_in[2];
    const int*   dst      = (const int*)d_in[3];
    const float* eps      = (const float*)d_in[4];
    const float* W1_first = (const float*)d_in[5];
    const float* b1_first = (const float*)d_in[6];
    const float* W1_rest  = (const float*)d_in[7];
    const float* b1_rest  = (const float*)d_in[8];
    const float* bn_gamma = (const float*)d_in[9];
    const float* bn_beta  = (const float*)d_in[10];
    const float* W2_mid   = (const float*)d_in[11];
    const float* b2_mid   = (const float*)d_in[12];
    const float* W2_last  = (const float*)d_in[13];
    const float* b2_last  = (const float*)d_in[14];
    float* pe = (float*)d_out;

    void *pHa, *pHb, *pW, *pStats, *pCf;
    cudaGetSymbolAddress(&pHa, g_Ha);
    cudaGetSymbolAddress(&pHb, g_Hb);
    cudaGetSymbolAddress(&pW, g_Wbf);
    cudaGetSymbolAddress(&pStats, g_stats);
    cudaGetSymbolAddress(&pCf, g_Cf);
    float* Ha = (float*)pHa;
    float* Hb = (float*)pHb;
    __nv_bfloat16* Wbf = (__nv_bfloat16*)pW;
    float* st = (float*)pStats;
    float* Cf = (float*)pCf;

    const int smA16 = (192 * 40) * 2 + 512;                    // 15872
    const int smG   = (192 * 264) * 2 + 2048;                  // 103424

    cudaFuncSetAttribute(gin_A16, cudaFuncAttributeMaxDynamicSharedMemorySize, smA16);
    cudaFuncSetAttribute(gin_G,   cudaFuncAttributeMaxDynamicSharedMemorySize, smG);

    // Launch order: setup1(1), setup2(2), A16(3), G(4) <- ncu captures #4
    gin_setup1<<<50, 1024>>>(src, dst, W1_rest, W2_mid, b2_mid);
    gin_setup2<<<50, 1024>>>(W1_first);

    gin_A16<<<GRID_MAIN, 256, smA16>>>(W, Wbf + OFF_W1F, b1_first, eps,
                                       Ha, st, st + 128);

    float* bufs[2] = { Ha, Hb };
    for (int l = 0; l < 3; l++) {
        gin_G<<<GRID_MAIN, 256, smG>>>(
            bufs[l & 1], Wbf + OFF_C(l),
            st + l * 256,                       // stats of H_{l+1 input}
            bn_gamma + (size_t)l * HID, bn_beta + (size_t)l * HID,
            eps, l + 1,
            b1_rest + (size_t)l * HID,          // b1 of layer l+1
            Cf + 3 * 16384 + l * 128,           // b2_mid[l]@W1_rest[l]
            bufs[(l + 1) & 1],
            st + (l + 1) * 256, st + (l + 1) * 256 + 128);
    }

    gin_KL<<<NSUM, 128>>>(bufs[1],              // H4 (after G3: Ha->Hb->Ha->Hb)
                          st + 3 * 256,
                          bn_gamma + 3 * (size_t)HID, bn_beta + 3 * (size_t)HID,
                          mask, W2_last, b2_last, pe);
}

// round 14
// speedup vs baseline: 3.2935x; 1.3627x over previous
#include <cuda_runtime.h>
#include <cuda_bf16.h>
#include <cstdint>

#define NSUM 2048
#define NMAX 64
#define MFEAT 16
#define HID 128
#define OUTF 64
#define NEDGE 16384
#define NROWS_TOTAL (NSUM * NMAX)
#define GRID_MAIN 296

// bf16 weight buffer: W1_first (K=16) + 3 combined C_l = W2_mid[l]@W1_rest[l] (K=128)
// n-major, stride = 2K+8, [hi K | lo K | pad]
#define SZ_W1F (128 * 40)
#define SZ_WR  (128 * 264)
#define OFF_W1F 0
#define OFF_C(l) (SZ_W1F + (l) * SZ_WR)
#define WBF_TOTAL (SZ_W1F + 3 * SZ_WR)

// ---------------------------------------------------------------------------
// Device scratch
// ---------------------------------------------------------------------------
__device__ float g_Ha[(size_t)NSUM * NMAX * HID];
__device__ float g_Hb[(size_t)NSUM * NMAX * HID];
__device__ float g_Y [(size_t)NSUM * NMAX * HID];
__device__ __nv_bfloat16 g_Wbf[WBF_TOTAL];
__device__ float g_Cf[3 * 16384 + 3 * 128];   // fp32 combined weights + b2@W1 vectors
__device__ float g_stats[4 * 2 * HID];
__device__ int   g_off[NSUM + 1];
__device__ int   g_csr[NEDGE];

// ---------------------------------------------------------------------------
// Setup1: CTA0 builds CSR + zeroes stats; CTAs 1..48 compute C_l = W2@W1 (fp32);
// CTA 49 computes bw_l = b2@W1.
// ---------------------------------------------------------------------------
__global__ void __launch_bounds__(1024)
gin_setup1(const int* __restrict__ src, const int* __restrict__ dst,
           const float* __restrict__ W1r, const float* __restrict__ W2m,
           const float* __restrict__ b2m)
{
    const int t = threadIdx.x;
    const int b = blockIdx.x;

    if (b >= 1 && b <= 48) {
        int idx = (b - 1) * 1024 + t;          // 0..49151
        int l = idx / 16384, r = idx % 16384;
        int k = r / 128, j = r % 128;
        const float* w2 = W2m + l * 16384 + k * 128;
        const float* w1 = W1r + l * 16384 + j;
        float s0 = 0.f, s1 = 0.f, s2 = 0.f, s3 = 0.f;
        #pragma unroll 8
        for (int m = 0; m < 128; m += 4) {
            s0 += w2[m]     * w1[(size_t)m * 128];
            s1 += w2[m + 1] * w1[(size_t)(m + 1) * 128];
            s2 += w2[m + 2] * w1[(size_t)(m + 2) * 128];
            s3 += w2[m + 3] * w1[(size_t)(m + 3) * 128];
        }
        g_Cf[idx] = (s0 + s1) + (s2 + s3);
        return;
    }
    if (b == 49) {
        if (t < 384) {
            int l = t / 128, j = t % 128;
            const float* bb = b2m + l * 128;
            const float* w1 = W1r + l * 16384 + j;
            float s = 0.f;
            #pragma unroll 8
            for (int m = 0; m < 128; m++) s += bb[m] * w1[(size_t)m * 128];
            g_Cf[3 * 16384 + t] = s;
        }
        return;
    }

    // ---- CTA 0: CSR build + zero stats ----
    __shared__ int s0[NSUM], s1[NSUM], cur[NSUM];
    g_stats[t] = 0.f;                     // 4*2*128 == 1024 exactly
    #pragma unroll
    for (int j = 0; j < 2; j++) { s0[t + j * 1024] = 0; cur[t + j * 1024] = 0; }
    __syncthreads();

    #pragma unroll
    for (int j = 0; j < NEDGE / 1024; j++)
        atomicAdd(&s0[dst[t + j * 1024]], 1);
    __syncthreads();

    int* in = s0; int* out = s1;
    for (int d = 1; d < NSUM; d <<= 1) {
        #pragma unroll
        for (int j = 0; j < 2; j++) {
            int i = t + j * 1024;
            int v = in[i];
            if (i >= d) v += in[i - d];
            out[i] = v;
        }
        __syncthreads();
        int* tmp = in; in = out; out = tmp;
    }
    if (t == 0) g_off[0] = 0;
    #pragma unroll
    for (int j = 0; j < 2; j++) g_off[t + j * 1024 + 1] = in[t + j * 1024];
    __syncthreads();

    #pragma unroll
    for (int j = 0; j < NEDGE / 1024; j++) {
        int e = t + j * 1024;
        int d = dst[e];
        int p = atomicAdd(&cur[d], 1);
        int off = d ? in[d - 1] : 0;
        g_csr[off + p] = src[e];
    }
}

// ---------------------------------------------------------------------------
// Setup2: convert W1_first + the three fp32 C matrices to bf16 hi/lo n-major.
// ---------------------------------------------------------------------------
__global__ void __launch_bounds__(1024)
gin_setup2(const float* __restrict__ W1f)
{
    int idx = blockIdx.x * 1024 + threadIdx.x;
    float w; int k, n, K; size_t doff; int sa;
    if (idx < 2048) {
        K = 16; k = idx / 128; n = idx % 128;
        w = W1f[idx]; doff = OFF_W1F; sa = 40;
    } else {
        int e = idx - 2048; int l = e / 16384; int r = e % 16384;
        K = 128; k = r / 128; n = r % 128;
        w = g_Cf[e]; doff = OFF_C(l); sa = 264;
    }
    __nv_bfloat16 hi = __float2bfloat16(w);
    __nv_bfloat16 lo = __float2bfloat16(w - __bfloat162float(hi));
    g_Wbf[doff + (size_t)n * sa + k]     = hi;
    g_Wbf[doff + (size_t)n * sa + K + k] = lo;
}

// ---------------------------------------------------------------------------
// MMA helpers
// ---------------------------------------------------------------------------
__device__ __forceinline__ void ldsm4(uint32_t* r, uint32_t a)
{
    asm volatile("ldmatrix.sync.aligned.m8n8.x4.shared.b16 {%0,%1,%2,%3}, [%4];"
                 : "=r"(r[0]), "=r"(r[1]), "=r"(r[2]), "=r"(r[3]) : "r"(a));
}

__device__ __forceinline__ void mma_bf16(float* d, const uint32_t* a, uint32_t b0, uint32_t b1)
{
    asm volatile("mma.sync.aligned.m16n8k16.row.col.f32.bf16.bf16.f32 "
                 "{%0,%1,%2,%3},{%4,%5,%6,%7},{%8,%9},{%0,%1,%2,%3};"
                 : "+f"(d[0]), "+f"(d[1]), "+f"(d[2]), "+f"(d[3])
                 : "r"(a[0]), "r"(a[1]), "r"(a[2]), "r"(a[3]), "r"(b0), "r"(b1));
}

// hi/lo bf16 convert + store of a float4 row-chunk
__device__ __forceinline__ void cvt_store(__nv_bfloat16* dhi, __nv_bfloat16* dlo, float4 v)
{
    __nv_bfloat16 h0 = __float2bfloat16(v.x), h1 = __float2bfloat16(v.y);
    __nv_bfloat16 h2 = __float2bfloat16(v.z), h3 = __float2bfloat16(v.w);
    __nv_bfloat162 a; a.x = h0; a.y = h1;
    __nv_bfloat162 b; b.x = h2; b.y = h3;
    ((__nv_bfloat162*)dhi)[0] = a; ((__nv_bfloat162*)dhi)[1] = b;
    __nv_bfloat162 c, d;
    c.x = __float2bfloat16(v.x - __bfloat162float(h0));
    c.y = __float2bfloat16(v.y - __bfloat162float(h1));
    d.x = __float2bfloat16(v.z - __bfloat162float(h2));
    d.y = __float2bfloat16(v.w - __bfloat162float(h3));
    ((__nv_bfloat162*)dlo)[0] = c; ((__nv_bfloat162*)dlo)[1] = d;
}

// GEMM core: 3 segments (hi*hi + lo*hi + hi*lo), KH/16 ksteps each.
template <int KH, int MT>
__device__ __forceinline__ void gemm_mma(const uint32_t* aBase, const uint32_t* bBase,
                                         int kaSel, int kbSel, float (*acc)[4][4])
{
    #pragma unroll
    for (int seg = 0; seg < 3; seg++) {
        const int aoff = (seg == 1) ? KH : 0;
        const int boff = (seg == 2) ? KH : 0;
        #pragma unroll
        for (int ks = 0; ks < KH / 16; ks++) {
            const int ka = (aoff + ks * 16 + kaSel) * 2;
            const int kb = (boff + ks * 16 + kbSel) * 2;
            uint32_t a[MT][4], b[2][4];
            #pragma unroll
            for (int mi = 0; mi < MT; mi++) ldsm4(a[mi], aBase[mi] + ka);
            #pragma unroll
            for (int p = 0; p < 2; p++) ldsm4(b[p], bBase[p] + kb);
            #pragma unroll
            for (int mi = 0; mi < MT; mi++)
                #pragma unroll
                for (int ni = 0; ni < 4; ni++)
                    mma_bf16(acc[mi][ni], a[mi], b[ni >> 1][(ni & 1) * 2], b[ni >> 1][(ni & 1) * 2 + 1]);
        }
    }
}

// ---------------------------------------------------------------------------
// Kernel A16 (layer 0 only): gather raw input W + GEMM1(16->128) + stats
// ---------------------------------------------------------------------------
__global__ void __launch_bounds__(256, 2)
gin_A16(const float* __restrict__ Xin, const __nv_bfloat16* __restrict__ Wg,
        const float* __restrict__ b1, const float* __restrict__ epsArr,
        float* __restrict__ Hout, float* __restrict__ gsum, float* __restrict__ gsq)
{
    constexpr int KH = 16, SA = 40, KC4 = 4, EPT = 1;
    extern __shared__ float smf[];
    __nv_bfloat16* Ws = (__nv_bfloat16*)smf;     // 128*40
    __nv_bfloat16* As = Ws + 128 * SA;           // 64*40
    float* sb = (float*)(As + 64 * SA);          // 128

    const int tid  = threadIdx.x;
    const int lane = tid & 31, wid = tid >> 5;
    const int wm = wid & 1, wn = wid >> 1;
    const int grp = lane >> 2, tig = lane & 3;
    const int sel = lane >> 3, l7 = lane & 7;
    const float epl = 1.f + epsArr[0];

    {
        const uint4* s = (const uint4*)Wg;
        uint4* d = (uint4*)Ws;
        for (int i = tid; i < 128 * SA / 8; i += 256) d[i] = s[i];
        if (tid < 128) sb[tid] = b1[tid];
    }

    uint32_t aBase[2], bBase[2];
    {
        uint32_t asb = (uint32_t)__cvta_generic_to_shared(As);
        uint32_t wsb = (uint32_t)__cvta_generic_to_shared(Ws);
        aBase[0] = asb + (uint32_t)((wm * 32 + l7 + (sel & 1) * 8) * SA) * 2;
        aBase[1] = aBase[0] + 16 * SA * 2;
        bBase[0] = wsb + (uint32_t)((wn * 32 + l7 + (sel >> 1) * 8) * SA) * 2;
        bBase[1] = bBase[0] + 16 * SA * 2;
    }
    const int kaSel = (sel >> 1) * 8, kbSel = (sel & 1) * 8;

    float psum[8], psq[8];
    #pragma unroll
    for (int q = 0; q < 8; q++) { psum[q] = 0.f; psq[q] = 0.f; }

    __syncthreads();

    for (int n = blockIdx.x; n < NSUM; n += GRID_MAIN) {
        float4 r[EPT];
        const float4* xn = (const float4*)(Xin + (size_t)n * 64 * KH);
        #pragma unroll
        for (int j = 0; j < EPT; j++) {
            float4 v = xn[tid + j * 256];
            r[j].x = v.x * epl; r[j].y = v.y * epl; r[j].z = v.z * epl; r[j].w = v.w * epl;
        }
        const int eE = g_off[n + 1];
        for (int e = g_off[n]; e < eE; e++) {
            const float4* xs = (const float4*)(Xin + (size_t)g_csr[e] * 64 * KH);
            #pragma unroll
            for (int j = 0; j < EPT; j++) {
                float4 v = xs[tid + j * 256];
                r[j].x += v.x; r[j].y += v.y; r[j].z += v.z; r[j].w += v.w;
            }
        }
        #pragma unroll
        for (int j = 0; j < EPT; j++) {
            int i = tid + j * 256;
            int row = i / KC4, col = (i % KC4) * 4;
            cvt_store(&As[row * SA + col], &As[row * SA + KH + col], r[j]);
        }
        __syncthreads();

        float acc[2][4][4];
        #pragma unroll
        for (int mi = 0; mi < 2; mi++)
            #pragma unroll
            for (int ni = 0; ni < 4; ni++) {
                int c0 = wn * 32 + ni * 8 + tig * 2;
                acc[mi][ni][0] = sb[c0];     acc[mi][ni][1] = sb[c0 + 1];
                acc[mi][ni][2] = sb[c0];     acc[mi][ni][3] = sb[c0 + 1];
            }
        gemm_mma<KH, 2>(aBase, bBase, kaSel, kbSel, acc);

        float* hb = Hout + (size_t)n * 64 * 128;
        #pragma unroll
        for (int mi = 0; mi < 2; mi++) {
            int r0 = wm * 32 + mi * 16 + grp;
            #pragma unroll
            for (int ni = 0; ni < 4; ni++) {
                int c0 = wn * 32 + ni * 8 + tig * 2;
                float2 v0 = make_float2(acc[mi][ni][0], acc[mi][ni][1]);
                float2 v1 = make_float2(acc[mi][ni][2], acc[mi][ni][3]);
                *(float2*)&hb[(size_t)r0 * 128 + c0]       = v0;
                *(float2*)&hb[(size_t)(r0 + 8) * 128 + c0] = v1;
                psum[ni * 2 + 0] += v0.x + v1.x;
                psum[ni * 2 + 1] += v0.y + v1.y;
                psq[ni * 2 + 0]  += v0.x * v0.x + v1.x * v1.x;
                psq[ni * 2 + 1]  += v0.y * v0.y + v1.y * v1.y;
            }
        }
        __syncthreads();
    }

    #pragma unroll
    for (int q = 0; q < 8; q++) {
        float s = psum[q], ss = psq[q];
        s  += __shfl_xor_sync(0xffffffffu, s, 4);
        s  += __shfl_xor_sync(0xffffffffu, s, 8);
        s  += __shfl_xor_sync(0xffffffffu, s, 16);
        ss += __shfl_xor_sync(0xffffffffu, ss, 4);
        ss += __shfl_xor_sync(0xffffffffu, ss, 8);
        ss += __shfl_xor_sync(0xffffffffu, ss, 16);
        if (lane < 4) {
            int c = wn * 32 + (q >> 1) * 8 + lane * 2 + (q & 1);
            atomicAdd(&gsum[c], s);
            atomicAdd(&gsq[c], ss);
        }
    }
}

// ---------------------------------------------------------------------------
// Kernel M (middle layers, GEMM phase): Y = relu(BN(H)) @ C
// Pure streaming: sequential H reads (last-use), Y written to stay L2-resident.
// ---------------------------------------------------------------------------
__global__ void __launch_bounds__(256, 2)
gin_M(const float* __restrict__ Hin, const __nv_bfloat16* __restrict__ Wg,
      const float* __restrict__ statsIn, const float* __restrict__ gamma,
      const float* __restrict__ beta, float* __restrict__ Yout)
{
    constexpr int KH = 128, SA = 264;
    extern __shared__ float smf[];
    __nv_bfloat16* Ws = (__nv_bfloat16*)smf;     // 128*264
    __nv_bfloat16* As = Ws + 128 * SA;           // 64*264
    float* ssc = (float*)(As + 64 * SA);         // 128
    float* ssh = ssc + 128;                      // 128

    const int tid  = threadIdx.x;
    const int lane = tid & 31, wid = tid >> 5;
    const int wm = wid & 1, wn = wid >> 1;
    const int grp = lane >> 2, tig = lane & 3;
    const int sel = lane >> 3, l7 = lane & 7;

    {
        const uint4* s = (const uint4*)Wg;
        uint4* d = (uint4*)Ws;
        for (int i = tid; i < 128 * SA / 8; i += 256) d[i] = s[i];
        if (tid < 128) {
            const float inv = 1.f / (float)NROWS_TOTAL;
            float mu  = statsIn[tid] * inv;
            float var = statsIn[128 + tid] * inv - mu * mu;
            float rs  = rsqrtf(var + 1e-5f);
            float scl = rs * gamma[tid];
            ssc[tid] = scl;
            ssh[tid] = beta[tid] - mu * scl;
        }
    }

    uint32_t aBase[2], bBase[2];
    {
        uint32_t asb = (uint32_t)__cvta_generic_to_shared(As);
        uint32_t wsb = (uint32_t)__cvta_generic_to_shared(Ws);
        aBase[0] = asb + (uint32_t)((wm * 32 + l7 + (sel & 1) * 8) * SA) * 2;
        aBase[1] = aBase[0] + 16 * SA * 2;
        bBase[0] = wsb + (uint32_t)((wn * 32 + l7 + (sel >> 1) * 8) * SA) * 2;
        bBase[1] = bBase[0] + 16 * SA * 2;
    }
    const int kaSel = (sel >> 1) * 8, kbSel = (sel & 1) * 8;

    __syncthreads();

    const int myc = (tid & 31) * 4;
    const float4 sc4 = *(const float4*)&ssc[myc];
    const float4 sh4 = *(const float4*)&ssh[myc];

    for (int n = blockIdx.x; n < NSUM; n += GRID_MAIN) {
        // ---- sequential read + BN + ReLU + hi/lo convert ----
        const float4* h4 = (const float4*)(Hin + (size_t)n * 8192);
        #pragma unroll
        for (int j = 0; j < 8; j++) {
            int i = tid + j * 256;
            int row = i >> 5;
            float4 v = __ldcs(&h4[i]);
            float4 a;
            a.x = fmaxf(fmaf(v.x, sc4.x, sh4.x), 0.f);
            a.y = fmaxf(fmaf(v.y, sc4.y, sh4.y), 0.f);
            a.z = fmaxf(fmaf(v.z, sc4.z, sh4.z), 0.f);
            a.w = fmaxf(fmaf(v.w, sc4.w, sh4.w), 0.f);
            cvt_store(&As[row * SA + myc], &As[row * SA + KH + myc], a);
        }
        __syncthreads();

        // ---- GEMM (zero-init accumulators; bias added in gather kernel) ----
        float acc[2][4][4];
        #pragma unroll
        for (int mi = 0; mi < 2; mi++)
            #pragma unroll
            for (int ni = 0; ni < 4; ni++)
                #pragma unroll
                for (int q = 0; q < 4; q++) acc[mi][ni][q] = 0.f;
        gemm_mma<KH, 2>(aBase, bBase, kaSel, kbSel, acc);

        // ---- write Y (default policy: keep in L2 for the gather kernel) ----
        float* yb = Yout + (size_t)n * 8192;
        #pragma unroll
        for (int mi = 0; mi < 2; mi++) {
            int r0 = wm * 32 + mi * 16 + grp;
            #pragma unroll
            for (int ni = 0; ni < 4; ni++) {
                int c0 = wn * 32 + ni * 8 + tig * 2;
                *(float2*)&yb[(size_t)r0 * 128 + c0]       = make_float2(acc[mi][ni][0], acc[mi][ni][1]);
                *(float2*)&yb[(size_t)(r0 + 8) * 128 + c0] = make_float2(acc[mi][ni][2], acc[mi][ni][3]);
            }
        }
        __syncthreads();
    }
}

// ---------------------------------------------------------------------------
// Kernel Gg (middle layers, gather phase): H_next[n] = (1+eps)Y[n] + sum Y[src]
//   + fac*(b2@W1) + b1, plus BN stats. One graph per CTA, no MMA, high occ.
// ---------------------------------------------------------------------------
__global__ void __launch_bounds__(256)
gin_Gg(const float* __restrict__ Y, const float* __restrict__ epsArr, int epsIdx,
       const float* __restrict__ b1v, const float* __restrict__ bwv,
       float* __restrict__ Hout, float* __restrict__ gsum, float* __restrict__ gsq)
{
    __shared__ float ssum[128], ssq[128];
    const int tid = threadIdx.x;
    const int n = blockIdx.x;
    const int myc = (tid & 31) * 4;

    if (tid < 128) { ssum[tid] = 0.f; ssq[tid] = 0.f; }

    const float epl = 1.f + epsArr[epsIdx];
    const int eB = g_off[n], eE = g_off[n + 1];
    const float fac = epl + (float)(eE - eB);

    float4 r[8];
    const float4* yn = (const float4*)(Y + (size_t)n * 8192);
    #pragma unroll
    for (int j = 0; j < 8; j++) {
        float4 v = yn[tid + j * 256];
        r[j].x = v.x * epl; r[j].y = v.y * epl; r[j].z = v.z * epl; r[j].w = v.w * epl;
    }
    for (int e = eB; e < eE; e++) {
        const float4* ys = (const float4*)(Y + (size_t)g_csr[e] * 8192);
        #pragma unroll
        for (int j = 0; j < 8; j++) {
            float4 v = ys[tid + j * 256];
            r[j].x += v.x; r[j].y += v.y; r[j].z += v.z; r[j].w += v.w;
        }
    }

    float4 bw4 = *(const float4*)(bwv + myc);
    float4 b14 = *(const float4*)(b1v + myc);
    float4 bias;
    bias.x = fmaf(fac, bw4.x, b14.x);
    bias.y = fmaf(fac, bw4.y, b14.y);
    bias.z = fmaf(fac, bw4.z, b14.z);
    bias.w = fmaf(fac, bw4.w, b14.w);

    float ps[4] = {0, 0, 0, 0}, pq[4] = {0, 0, 0, 0};
    float4* hb = (float4*)(Hout + (size_t)n * 8192);
    #pragma unroll
    for (int j = 0; j < 8; j++) {
        r[j].x += bias.x; r[j].y += bias.y; r[j].z += bias.z; r[j].w += bias.w;
        __stcs(&hb[tid + j * 256], r[j]);
        ps[0] += r[j].x; ps[1] += r[j].y; ps[2] += r[j].z; ps[3] += r[j].w;
        pq[0] += r[j].x * r[j].x; pq[1] += r[j].y * r[j].y;
        pq[2] += r[j].z * r[j].z; pq[3] += r[j].w * r[j].w;
    }

    __syncthreads();
    #pragma unroll
    for (int c = 0; c < 4; c++) {
        atomicAdd(&ssum[myc + c], ps[c]);
        atomicAdd(&ssq[myc + c], pq[c]);
    }
    __syncthreads();
    if (tid < 128) {
        atomicAdd(&gsum[tid], ssum[tid]);
        atomicAdd(&gsq[tid], ssq[tid]);
    }
}

// ---------------------------------------------------------------------------
// Kernel KL (last layer): PE[n] = (Σ_r mask*relu(bn(H4)))@W2_last + (Σmask)*b2
// ---------------------------------------------------------------------------
__global__ void __launch_bounds__(128)
gin_KL(const float* __restrict__ H4, const float* __restrict__ statsIn,
       const float* __restrict__ gamma, const float* __restrict__ beta,
       const float* __restrict__ mask, const float* __restrict__ W2L,
       const float* __restrict__ b2L, float* __restrict__ pe)
{
    __shared__ float v[128];
    __shared__ float smt;
    const int n = blockIdx.x;
    const int c = threadIdx.x;

    const float inv = 1.f / (float)NROWS_TOTAL;
    float mu  = statsIn[c] * inv;
    float var = statsIn[128 + c] * inv - mu * mu;
    float rs  = rsqrtf(var + 1e-5f);
    float sc  = rs * gamma[c];
    float sh  = beta[c] - mu * sc;

    const float* hb = H4 + (size_t)n * 8192 + c;
    const float* mb = mask + (size_t)n * 64;
    float a0 = 0.f, a1 = 0.f, a2 = 0.f, a3 = 0.f, mt = 0.f;
    #pragma unroll 4
    for (int r = 0; r < 64; r += 4) {
        float mA = mb[r], mB = mb[r + 1], mC = mb[r + 2], mD = mb[r + 3];
        a0 += mA * fmaxf(fmaf(hb[(size_t)r * 128],       sc, sh), 0.f);
        a1 += mB * fmaxf(fmaf(hb[(size_t)(r + 1) * 128], sc, sh), 0.f);
        a2 += mC * fmaxf(fmaf(hb[(size_t)(r + 2) * 128], sc, sh), 0.f);
        a3 += mD * fmaxf(fmaf(hb[(size_t)(r + 3) * 128], sc, sh), 0.f);
        mt += mA + mB + mC + mD;
    }
    v[c] = (a0 + a1) + (a2 + a3);
    if (c == 0) smt = mt;
    __syncthreads();

    if (c < OUTF) {
        float acc0 = smt * b2L[c], acc1 = 0.f, acc2 = 0.f, acc3 = 0.f;
        #pragma unroll 8
        for (int k = 0; k < 128; k += 4) {
            acc0 += v[k]     * W2L[(size_t)k * 64 + c];
            acc1 += v[k + 1] * W2L[(size_t)(k + 1) * 64 + c];
            acc2 += v[k + 2] * W2L[(size_t)(k + 2) * 64 + c];
            acc3 += v[k + 3] * W2L[(size_t)(k + 3) * 64 + c];
        }
        pe[(size_t)n * 64 + c] = (acc0 + acc1) + (acc2 + acc3);
    }
}

// ---------------------------------------------------------------------------
// Host-side launch
// ---------------------------------------------------------------------------
extern "C" void kernel_launch(void* const* d_in, const int* in_sizes, int n_in,
                              void* d_out, int out_size)
{
    const float* W        = (const float*)d_in[0];
    const float* mask     = (const float*)d_in[1];
    const int*   src      = (const int*)d_in[2];
    const int*   dst      = (const int*)d_in[3];
    const float* eps      = (const float*)d_in[4];
    const float* W1_first = (const float*)d_in[5];
    const float* b1_first = (const float*)d_in[6];
    const float* W1_rest  = (const float*)d_in[7];
    const float* b1_rest  = (const float*)d_in[8];
    const float* bn_gamma = (const float*)d_in[9];
    const float* bn_beta  = (const float*)d_in[10];
    const float* W2_mid   = (const float*)d_in[11];
    const float* b2_mid   = (const float*)d_in[12];
    const float* W2_last  = (const float*)d_in[13];
    const float* b2_last  = (const float*)d_in[14];
    float* pe = (float*)d_out;

    void *pHa, *pHb, *pY, *pW, *pStats, *pCf;
    cudaGetSymbolAddress(&pHa, g_Ha);
    cudaGetSymbolAddress(&pHb, g_Hb);
    cudaGetSymbolAddress(&pY, g_Y);
    cudaGetSymbolAddress(&pW, g_Wbf);
    cudaGetSymbolAddress(&pStats, g_stats);
    cudaGetSymbolAddress(&pCf, g_Cf);
    float* Ha = (float*)pHa;
    float* Hb = (float*)pHb;
    float* Yb = (float*)pY;
    __nv_bfloat16* Wbf = (__nv_bfloat16*)pW;
    float* st = (float*)pStats;
    float* Cf = (float*)pCf;

    const int smA16 = (192 * 40) * 2 + 512;                    // 15872
    const int smM   = (192 * 264) * 2 + 1024;                  // 102400

    cudaFuncSetAttribute(gin_A16, cudaFuncAttributeMaxDynamicSharedMemorySize, smA16);
    cudaFuncSetAttribute(gin_M,   cudaFuncAttributeMaxDynamicSharedMemorySize, smM);

    // Launch order: setup1(1), setup2(2), A16(3), M(4) <- ncu captures #4
    gin_setup1<<<50, 1024>>>(src, dst, W1_rest, W2_mid, b2_mid);
    gin_setup2<<<50, 1024>>>(W1_first);

    gin_A16<<<GRID_MAIN, 256, smA16>>>(W, Wbf + OFF_W1F, b1_first, eps,
                                       Ha, st, st + 128);

    float* bufs[2] = { Ha, Hb };
    for (int l = 0; l < 3; l++) {
        gin_M<<<GRID_MAIN, 256, smM>>>(
            bufs[l & 1], Wbf + OFF_C(l),
            st + l * 256,
            bn_gamma + (size_t)l * HID, bn_beta + (size_t)l * HID,
            Yb);
        gin_Gg<<<NSUM, 256>>>(
            Yb, eps, l + 1,
            b1_rest + (size_t)l * HID,
            Cf + 3 * 16384 + l * 128,
            bufs[(l + 1) & 1],
            st + (l + 1) * 256, st + (l + 1) * 256 + 128);
    }

    gin_KL<<<NSUM, 128>>>(bufs[1],              // H4 (Ha->Hb->Ha->Hb)
                          st + 3 * 256,
                          bn_gamma + 3 * (size_t)HID, bn_beta + 3 * (size_t)HID,
                          mask, W2_last, b2_last, pe);
}

// round 15
// speedup vs baseline: 3.5220x; 1.0694x over previous
#include <cuda_runtime.h>
#include <cuda_bf16.h>
#include <cstdint>

#define NSUM 2048
#define NMAX 64
#define MFEAT 16
#define HID 128
#define OUTF 64
#define NEDGE 16384
#define NROWS_TOTAL (NSUM * NMAX)
#define GRID_MAIN 296
#define GRID_M 148
#define NPAIR 1024

// bf16 weight buffer: W1_first (K=16) + 3 combined C_l = W2_mid[l]@W1_rest[l] (K=128)
// n-major, stride = 2K+8, [hi K | lo K | pad]
#define SZ_W1F (128 * 40)
#define SZ_WR  (128 * 264)
#define OFF_W1F 0
#define OFF_C(l) (SZ_W1F + (l) * SZ_WR)
#define WBF_TOTAL (SZ_W1F + 3 * SZ_WR)

// ---------------------------------------------------------------------------
// Device scratch
// ---------------------------------------------------------------------------
__device__ float g_Ha[(size_t)NSUM * NMAX * HID];
__device__ float g_Hb[(size_t)NSUM * NMAX * HID];
__device__ float g_Y [(size_t)NSUM * NMAX * HID];
__device__ __nv_bfloat16 g_Wbf[WBF_TOTAL];
__device__ float g_Cf[3 * 16384 + 3 * 128];   // fp32 combined weights + b2@W1 vectors
__device__ float g_stats[4 * 2 * HID];
__device__ int   g_off[NSUM + 1];
__device__ int   g_csr[NEDGE];

// ---------------------------------------------------------------------------
// Setup1: CTA0 builds CSR + zeroes stats; CTAs 1..48 compute C_l = W2@W1 (fp32);
// CTA 49 computes bw_l = b2@W1.
// ---------------------------------------------------------------------------
__global__ void __launch_bounds__(1024)
gin_setup1(const int* __restrict__ src, const int* __restrict__ dst,
           const float* __restrict__ W1r, const float* __restrict__ W2m,
           const float* __restrict__ b2m)
{
    const int t = threadIdx.x;
    const int b = blockIdx.x;

    if (b >= 1 && b <= 48) {
        int idx = (b - 1) * 1024 + t;          // 0..49151
        int l = idx / 16384, r = idx % 16384;
        int k = r / 128, j = r % 128;
        const float* w2 = W2m + l * 16384 + k * 128;
        const float* w1 = W1r + l * 16384 + j;
        float s0 = 0.f, s1 = 0.f, s2 = 0.f, s3 = 0.f;
        #pragma unroll 8
        for (int m = 0; m < 128; m += 4) {
            s0 += w2[m]     * w1[(size_t)m * 128];
            s1 += w2[m + 1] * w1[(size_t)(m + 1) * 128];
            s2 += w2[m + 2] * w1[(size_t)(m + 2) * 128];
            s3 += w2[m + 3] * w1[(size_t)(m + 3) * 128];
        }
        g_Cf[idx] = (s0 + s1) + (s2 + s3);
        return;
    }
    if (b == 49) {
        if (t < 384) {
            int l = t / 128, j = t % 128;
            const float* bb = b2m + l * 128;
            const float* w1 = W1r + l * 16384 + j;
            float s = 0.f;
            #pragma unroll 8
            for (int m = 0; m < 128; m++) s += bb[m] * w1[(size_t)m * 128];
            g_Cf[3 * 16384 + t] = s;
        }
        return;
    }

    // ---- CTA 0: CSR build + zero stats ----
    __shared__ int s0[NSUM], s1[NSUM], cur[NSUM];
    g_stats[t] = 0.f;                     // 4*2*128 == 1024 exactly
    #pragma unroll
    for (int j = 0; j < 2; j++) { s0[t + j * 1024] = 0; cur[t + j * 1024] = 0; }
    __syncthreads();

    #pragma unroll
    for (int j = 0; j < NEDGE / 1024; j++)
        atomicAdd(&s0[dst[t + j * 1024]], 1);
    __syncthreads();

    int* in = s0; int* out = s1;
    for (int d = 1; d < NSUM; d <<= 1) {
        #pragma unroll
        for (int j = 0; j < 2; j++) {
            int i = t + j * 1024;
            int v = in[i];
            if (i >= d) v += in[i - d];
            out[i] = v;
        }
        __syncthreads();
        int* tmp = in; in = out; out = tmp;
    }
    if (t == 0) g_off[0] = 0;
    #pragma unroll
    for (int j = 0; j < 2; j++) g_off[t + j * 1024 + 1] = in[t + j * 1024];
    __syncthreads();

    #pragma unroll
    for (int j = 0; j < NEDGE / 1024; j++) {
        int e = t + j * 1024;
        int d = dst[e];
        int p = atomicAdd(&cur[d], 1);
        int off = d ? in[d - 1] : 0;
        g_csr[off + p] = src[e];
    }
}

// ---------------------------------------------------------------------------
// Setup2: convert W1_first + the three fp32 C matrices to bf16 hi/lo n-major.
// ---------------------------------------------------------------------------
__global__ void __launch_bounds__(1024)
gin_setup2(const float* __restrict__ W1f)
{
    int idx = blockIdx.x * 1024 + threadIdx.x;
    float w; int k, n, K; size_t doff; int sa;
    if (idx < 2048) {
        K = 16; k = idx / 128; n = idx % 128;
        w = W1f[idx]; doff = OFF_W1F; sa = 40;
    } else {
        int e = idx - 2048; int l = e / 16384; int r = e % 16384;
        K = 128; k = r / 128; n = r % 128;
        w = g_Cf[e]; doff = OFF_C(l); sa = 264;
    }
    __nv_bfloat16 hi = __float2bfloat16(w);
    __nv_bfloat16 lo = __float2bfloat16(w - __bfloat162float(hi));
    g_Wbf[doff + (size_t)n * sa + k]     = hi;
    g_Wbf[doff + (size_t)n * sa + K + k] = lo;
}

// ---------------------------------------------------------------------------
// MMA / async-copy helpers
// ---------------------------------------------------------------------------
__device__ __forceinline__ void ldsm4(uint32_t* r, uint32_t a)
{
    asm volatile("ldmatrix.sync.aligned.m8n8.x4.shared.b16 {%0,%1,%2,%3}, [%4];"
                 : "=r"(r[0]), "=r"(r[1]), "=r"(r[2]), "=r"(r[3]) : "r"(a));
}

__device__ __forceinline__ void mma_bf16(float* d, const uint32_t* a, uint32_t b0, uint32_t b1)
{
    asm volatile("mma.sync.aligned.m16n8k16.row.col.f32.bf16.bf16.f32 "
                 "{%0,%1,%2,%3},{%4,%5,%6,%7},{%8,%9},{%0,%1,%2,%3};"
                 : "+f"(d[0]), "+f"(d[1]), "+f"(d[2]), "+f"(d[3])
                 : "r"(a[0]), "r"(a[1]), "r"(a[2]), "r"(a[3]), "r"(b0), "r"(b1));
}

__device__ __forceinline__ void cp_async16(uint32_t dst, const void* src)
{
    asm volatile("cp.async.cg.shared.global [%0], [%1], 16;" :: "r"(dst), "l"(src));
}
#define CP_COMMIT() asm volatile("cp.async.commit_group;" ::: "memory")
#define CP_WAIT0()  asm volatile("cp.async.wait_group 0;" ::: "memory")

// hi/lo bf16 convert + store of a float4 row-chunk
__device__ __forceinline__ void cvt_store(__nv_bfloat16* dhi, __nv_bfloat16* dlo, float4 v)
{
    __nv_bfloat16 h0 = __float2bfloat16(v.x), h1 = __float2bfloat16(v.y);
    __nv_bfloat16 h2 = __float2bfloat16(v.z), h3 = __float2bfloat16(v.w);
    __nv_bfloat162 a; a.x = h0; a.y = h1;
    __nv_bfloat162 b; b.x = h2; b.y = h3;
    ((__nv_bfloat162*)dhi)[0] = a; ((__nv_bfloat162*)dhi)[1] = b;
    __nv_bfloat162 c, d;
    c.x = __float2bfloat16(v.x - __bfloat162float(h0));
    c.y = __float2bfloat16(v.y - __bfloat162float(h1));
    d.x = __float2bfloat16(v.z - __bfloat162float(h2));
    d.y = __float2bfloat16(v.w - __bfloat162float(h3));
    ((__nv_bfloat162*)dlo)[0] = c; ((__nv_bfloat162*)dlo)[1] = d;
}

// GEMM core: 3 segments (hi*hi + lo*hi + hi*lo), KH/16 ksteps each.
template <int KH, int MT>
__device__ __forceinline__ void gemm_mma(const uint32_t* aBase, const uint32_t* bBase,
                                         int kaSel, int kbSel, float (*acc)[4][4])
{
    #pragma unroll
    for (int seg = 0; seg < 3; seg++) {
        const int aoff = (seg == 1) ? KH : 0;
        const int boff = (seg == 2) ? KH : 0;
        #pragma unroll
        for (int ks = 0; ks < KH / 16; ks++) {
            const int ka = (aoff + ks * 16 + kaSel) * 2;
            const int kb = (boff + ks * 16 + kbSel) * 2;
            uint32_t a[MT][4], b[2][4];
            #pragma unroll
            for (int mi = 0; mi < MT; mi++) ldsm4(a[mi], aBase[mi] + ka);
            #pragma unroll
            for (int p = 0; p < 2; p++) ldsm4(b[p], bBase[p] + kb);
            #pragma unroll
            for (int mi = 0; mi < MT; mi++)
                #pragma unroll
                for (int ni = 0; ni < 4; ni++)
                    mma_bf16(acc[mi][ni], a[mi], b[ni >> 1][(ni & 1) * 2], b[ni >> 1][(ni & 1) * 2 + 1]);
        }
    }
}

// ---------------------------------------------------------------------------
// Kernel A16 (layer 0 only): gather raw input W + GEMM1(16->128) + stats
// ---------------------------------------------------------------------------
__global__ void __launch_bounds__(256, 2)
gin_A16(const float* __restrict__ Xin, const __nv_bfloat16* __restrict__ Wg,
        const float* __restrict__ b1, const float* __restrict__ epsArr,
        float* __restrict__ Hout, float* __restrict__ gsum, float* __restrict__ gsq)
{
    constexpr int KH = 16, SA = 40, KC4 = 4, EPT = 1;
    extern __shared__ float smf[];
    __nv_bfloat16* Ws = (__nv_bfloat16*)smf;     // 128*40
    __nv_bfloat16* As = Ws + 128 * SA;           // 64*40
    float* sb = (float*)(As + 64 * SA);          // 128

    const int tid  = threadIdx.x;
    const int lane = tid & 31, wid = tid >> 5;
    const int wm = wid & 1, wn = wid >> 1;
    const int grp = lane >> 2, tig = lane & 3;
    const int sel = lane >> 3, l7 = lane & 7;
    const float epl = 1.f + epsArr[0];

    {
        const uint4* s = (const uint4*)Wg;
        uint4* d = (uint4*)Ws;
        for (int i = tid; i < 128 * SA / 8; i += 256) d[i] = s[i];
        if (tid < 128) sb[tid] = b1[tid];
    }

    uint32_t aBase[2], bBase[2];
    {
        uint32_t asb = (uint32_t)__cvta_generic_to_shared(As);
        uint32_t wsb = (uint32_t)__cvta_generic_to_shared(Ws);
        aBase[0] = asb + (uint32_t)((wm * 32 + l7 + (sel & 1) * 8) * SA) * 2;
        aBase[1] = aBase[0] + 16 * SA * 2;
        bBase[0] = wsb + (uint32_t)((wn * 32 + l7 + (sel >> 1) * 8) * SA) * 2;
        bBase[1] = bBase[0] + 16 * SA * 2;
    }
    const int kaSel = (sel >> 1) * 8, kbSel = (sel & 1) * 8;

    float psum[8], psq[8];
    #pragma unroll
    for (int q = 0; q < 8; q++) { psum[q] = 0.f; psq[q] = 0.f; }

    __syncthreads();

    for (int n = blockIdx.x; n < NSUM; n += GRID_MAIN) {
        float4 r[EPT];
        const float4* xn = (const float4*)(Xin + (size_t)n * 64 * KH);
        #pragma unroll
        for (int j = 0; j < EPT; j++) {
            float4 v = xn[tid + j * 256];
            r[j].x = v.x * epl; r[j].y = v.y * epl; r[j].z = v.z * epl; r[j].w = v.w * epl;
        }
        const int eE = g_off[n + 1];
        for (int e = g_off[n]; e < eE; e++) {
            const float4* xs = (const float4*)(Xin + (size_t)g_csr[e] * 64 * KH);
            #pragma unroll
            for (int j = 0; j < EPT; j++) {
                float4 v = xs[tid + j * 256];
                r[j].x += v.x; r[j].y += v.y; r[j].z += v.z; r[j].w += v.w;
            }
        }
        #pragma unroll
        for (int j = 0; j < EPT; j++) {
            int i = tid + j * 256;
            int row = i / KC4, col = (i % KC4) * 4;
            cvt_store(&As[row * SA + col], &As[row * SA + KH + col], r[j]);
        }
        __syncthreads();

        float acc[2][4][4];
        #pragma unroll
        for (int mi = 0; mi < 2; mi++)
            #pragma unroll
            for (int ni = 0; ni < 4; ni++) {
                int c0 = wn * 32 + ni * 8 + tig * 2;
                acc[mi][ni][0] = sb[c0];     acc[mi][ni][1] = sb[c0 + 1];
                acc[mi][ni][2] = sb[c0];     acc[mi][ni][3] = sb[c0 + 1];
            }
        gemm_mma<KH, 2>(aBase, bBase, kaSel, kbSel, acc);

        float* hb = Hout + (size_t)n * 64 * 128;
        #pragma unroll
        for (int mi = 0; mi < 2; mi++) {
            int r0 = wm * 32 + mi * 16 + grp;
            #pragma unroll
            for (int ni = 0; ni < 4; ni++) {
                int c0 = wn * 32 + ni * 8 + tig * 2;
                float2 v0 = make_float2(acc[mi][ni][0], acc[mi][ni][1]);
                float2 v1 = make_float2(acc[mi][ni][2], acc[mi][ni][3]);
                *(float2*)&hb[(size_t)r0 * 128 + c0]       = v0;
                *(float2*)&hb[(size_t)(r0 + 8) * 128 + c0] = v1;
                psum[ni * 2 + 0] += v0.x + v1.x;
                psum[ni * 2 + 1] += v0.y + v1.y;
                psq[ni * 2 + 0]  += v0.x * v0.x + v1.x * v1.x;
                psq[ni * 2 + 1]  += v0.y * v0.y + v1.y * v1.y;
            }
        }
        __syncthreads();
    }

    #pragma unroll
    for (int q = 0; q < 8; q++) {
        float s = psum[q], ss = psq[q];
        s  += __shfl_xor_sync(0xffffffffu, s, 4);
        s  += __shfl_xor_sync(0xffffffffu, s, 8);
        s  += __shfl_xor_sync(0xffffffffu, s, 16);
        ss += __shfl_xor_sync(0xffffffffu, ss, 4);
        ss += __shfl_xor_sync(0xffffffffu, ss, 8);
        ss += __shfl_xor_sync(0xffffffffu, ss, 16);
        if (lane < 4) {
            int c = wn * 32 + (q >> 1) * 8 + lane * 2 + (q & 1);
            atomicAdd(&gsum[c], s);
            atomicAdd(&gsq[c], ss);
        }
    }
}

// ---------------------------------------------------------------------------
// Kernel M (middle layers, GEMM phase): Y = relu(BN(H)) @ C
// 2-graph tiles (M=128), 512 threads, 1 CTA/SM, 4m x 4n warps.
// Next H tile prefetched via cp.async into a smem stage (no register pressure).
// ---------------------------------------------------------------------------
__global__ void __launch_bounds__(512, 1)
gin_M(const float* __restrict__ Hin, const __nv_bfloat16* __restrict__ Wg,
      const float* __restrict__ statsIn, const float* __restrict__ gamma,
      const float* __restrict__ beta, float* __restrict__ Yout)
{
    constexpr int KH = 128, SA = 264;
    extern __shared__ char smc[];
    __nv_bfloat16* Ws = (__nv_bfloat16*)smc;                 // 128*264*2 = 67584 B
    __nv_bfloat16* As = (__nv_bfloat16*)(smc + 67584);       // 128*264*2 = 67584 B
    float* stage = (float*)(smc + 135168);                   // 2 graphs fp32 = 65536 B
    float* ssc = (float*)(smc + 200704);                     // 128
    float* ssh = ssc + 128;                                  // 128

    const int tid  = threadIdx.x;
    const int lane = tid & 31, wid = tid >> 5;
    const int wm = wid & 3, wn = wid >> 2;   // 4 (m) x 4 (n) warps
    const int grp = lane >> 2, tig = lane & 3;
    const int sel = lane >> 3, l7 = lane & 7;

    {
        const uint4* s = (const uint4*)Wg;
        uint4* d = (uint4*)Ws;
        for (int i = tid; i < 128 * SA / 8; i += 512) d[i] = s[i];
        if (tid < 128) {
            const float inv = 1.f / (float)NROWS_TOTAL;
            float mu  = statsIn[tid] * inv;
            float var = statsIn[128 + tid] * inv - mu * mu;
            float rs  = rsqrtf(var + 1e-5f);
            float scl = rs * gamma[tid];
            ssc[tid] = scl;
            ssh[tid] = beta[tid] - mu * scl;
        }
    }

    uint32_t aBase[2], bBase[2];
    {
        uint32_t asb = (uint32_t)__cvta_generic_to_shared(As);
        uint32_t wsb = (uint32_t)__cvta_generic_to_shared(Ws);
        aBase[0] = asb + (uint32_t)((wm * 32 + l7 + (sel & 1) * 8) * SA) * 2;
        aBase[1] = aBase[0] + 16 * SA * 2;
        bBase[0] = wsb + (uint32_t)((wn * 32 + l7 + (sel >> 1) * 8) * SA) * 2;
        bBase[1] = bBase[0] + 16 * SA * 2;
    }
    const int kaSel = (sel >> 1) * 8, kbSel = (sel & 1) * 8;

    const uint32_t stg = (uint32_t)__cvta_generic_to_shared(stage);
    const int myc = (tid & 31) * 4;

    // prologue: stage first tile-pair
    int p = blockIdx.x;
    if (p < NPAIR) {
        #pragma unroll
        for (int j = 0; j < 8; j++) {
            int i = tid + j * 512;
            cp_async16(stg + (uint32_t)i * 16, Hin + (size_t)p * 16384 + (size_t)i * 4);
        }
    }
    CP_COMMIT();
    __syncthreads();                       // Ws / ssc ready

    const float4 sc4 = *(const float4*)&ssc[myc];
    const float4 sh4 = *(const float4*)&ssh[myc];

    for (; p < NPAIR; p += GRID_M) {
        CP_WAIT0();
        __syncthreads();                   // stage ready (all threads' copies)

        // ---- BN + ReLU + hi/lo convert stage -> As ----
        const float4* st4 = (const float4*)stage;
        #pragma unroll
        for (int j = 0; j < 8; j++) {
            int i = tid + j * 512;
            int row = i >> 5;
            float4 v = st4[i];
            float4 a;
            a.x = fmaxf(fmaf(v.x, sc4.x, sh4.x), 0.f);
            a.y = fmaxf(fmaf(v.y, sc4.y, sh4.y), 0.f);
            a.z = fmaxf(fmaf(v.z, sc4.z, sh4.z), 0.f);
            a.w = fmaxf(fmaf(v.w, sc4.w, sh4.w), 0.f);
            cvt_store(&As[row * SA + myc], &As[row * SA + KH + myc], a);
        }
        __syncthreads();                   // As ready; stage free

        // ---- prefetch next tile-pair while GEMM runs ----
        const int pn = p + GRID_M;
        if (pn < NPAIR) {
            #pragma unroll
            for (int j = 0; j < 8; j++) {
                int i = tid + j * 512;
                cp_async16(stg + (uint32_t)i * 16, Hin + (size_t)pn * 16384 + (size_t)i * 4);
            }
        }
        CP_COMMIT();

        // ---- GEMM (zero-init; bias added in gather kernel) ----
        float acc[2][4][4];
        #pragma unroll
        for (int mi = 0; mi < 2; mi++)
            #pragma unroll
            for (int ni = 0; ni < 4; ni++)
                #pragma unroll
                for (int q = 0; q < 4; q++) acc[mi][ni][q] = 0.f;
        gemm_mma<KH, 2>(aBase, bBase, kaSel, kbSel, acc);

        // ---- write Y ----
        #pragma unroll
        for (int mi = 0; mi < 2; mi++) {
            int r0 = wm * 32 + mi * 16 + grp;            // 0..127
            float* yb = Yout + (size_t)(p * 2 + (r0 >> 6)) * 8192 + (size_t)(r0 & 63) * 128;
            #pragma unroll
            for (int ni = 0; ni < 4; ni++) {
                int c0 = wn * 32 + ni * 8 + tig * 2;
                *(float2*)&yb[c0]            = make_float2(acc[mi][ni][0], acc[mi][ni][1]);
                *(float2*)&yb[8 * 128 + c0]  = make_float2(acc[mi][ni][2], acc[mi][ni][3]);
            }
        }
    }
}

// ---------------------------------------------------------------------------
// Kernel Gg (middle layers, gather phase): H_next[n] = (1+eps)Y[n] + sum Y[src]
//   + fac*(b2@W1) + b1, plus BN stats. One graph per CTA, no MMA, high occ.
// ---------------------------------------------------------------------------
__global__ void __launch_bounds__(256)
gin_Gg(const float* __restrict__ Y, const float* __restrict__ epsArr, int epsIdx,
       const float* __restrict__ b1v, const float* __restrict__ bwv,
       float* __restrict__ Hout, float* __restrict__ gsum, float* __restrict__ gsq)
{
    __shared__ float ssum[128], ssq[128];
    const int tid = threadIdx.x;
    const int n = blockIdx.x;
    const int myc = (tid & 31) * 4;

    if (tid < 128) { ssum[tid] = 0.f; ssq[tid] = 0.f; }

    const float epl = 1.f + epsArr[epsIdx];
    const int eB = g_off[n], eE = g_off[n + 1];
    const float fac = epl + (float)(eE - eB);

    float4 r[8];
    const float4* yn = (const float4*)(Y + (size_t)n * 8192);
    #pragma unroll
    for (int j = 0; j < 8; j++) {
        float4 v = yn[tid + j * 256];
        r[j].x = v.x * epl; r[j].y = v.y * epl; r[j].z = v.z * epl; r[j].w = v.w * epl;
    }
    for (int e = eB; e < eE; e++) {
        const float4* ys = (const float4*)(Y + (size_t)g_csr[e] * 8192);
        #pragma unroll
        for (int j = 0; j < 8; j++) {
            float4 v = ys[tid + j * 256];
            r[j].x += v.x; r[j].y += v.y; r[j].z += v.z; r[j].w += v.w;
        }
    }

    float4 bw4 = *(const float4*)(bwv + myc);
    float4 b14 = *(const float4*)(b1v + myc);
    float4 bias;
    bias.x = fmaf(fac, bw4.x, b14.x);
    bias.y = fmaf(fac, bw4.y, b14.y);
    bias.z = fmaf(fac, bw4.z, b14.z);
    bias.w = fmaf(fac, bw4.w, b14.w);

    float ps[4] = {0, 0, 0, 0}, pq[4] = {0, 0, 0, 0};
    float4* hb = (float4*)(Hout + (size_t)n * 8192);
    #pragma unroll
    for (int j = 0; j < 8; j++) {
        r[j].x += bias.x; r[j].y += bias.y; r[j].z += bias.z; r[j].w += bias.w;
        __stcs(&hb[tid + j * 256], r[j]);
        ps[0] += r[j].x; ps[1] += r[j].y; ps[2] += r[j].z; ps[3] += r[j].w;
        pq[0] += r[j].x * r[j].x; pq[1] += r[j].y * r[j].y;
        pq[2] += r[j].z * r[j].z; pq[3] += r[j].w * r[j].w;
    }

    __syncthreads();
    #pragma unroll
    for (int c = 0; c < 4; c++) {
        atomicAdd(&ssum[myc + c], ps[c]);
        atomicAdd(&ssq[myc + c], pq[c]);
    }
    __syncthreads();
    if (tid < 128) {
        atomicAdd(&gsum[tid], ssum[tid]);
        atomicAdd(&gsq[tid], ssq[tid]);
    }
}

// ---------------------------------------------------------------------------
// Kernel KL (last layer): PE[n] = (Σ_r mask*relu(bn(H4)))@W2_last + (Σmask)*b2
// ---------------------------------------------------------------------------
__global__ void __launch_bounds__(128)
gin_KL(const float* __restrict__ H4, const float* __restrict__ statsIn,
       const float* __restrict__ gamma, const float* __restrict__ beta,
       const float* __restrict__ mask, const float* __restrict__ W2L,
       const float* __restrict__ b2L, float* __restrict__ pe)
{
    __shared__ float v[128];
    __shared__ float smt;
    const int n = blockIdx.x;
    const int c = threadIdx.x;

    const float inv = 1.f / (float)NROWS_TOTAL;
    float mu  = statsIn[c] * inv;
    float var = statsIn[128 + c] * inv - mu * mu;
    float rs  = rsqrtf(var + 1e-5f);
    float sc  = rs * gamma[c];
    float sh  = beta[c] - mu * sc;

    const float* hb = H4 + (size_t)n * 8192 + c;
    const float* mb = mask + (size_t)n * 64;
    float a0 = 0.f, a1 = 0.f, a2 = 0.f, a3 = 0.f, mt = 0.f;
    #pragma unroll 4
    for (int r = 0; r < 64; r += 4) {
        float mA = mb[r], mB = mb[r + 1], mC = mb[r + 2], mD = mb[r + 3];
        a0 += mA * fmaxf(fmaf(hb[(size_t)r * 128],       sc, sh), 0.f);
        a1 += mB * fmaxf(fmaf(hb[(size_t)(r + 1) * 128], sc, sh), 0.f);
        a2 += mC * fmaxf(fmaf(hb[(size_t)(r + 2) * 128], sc, sh), 0.f);
        a3 += mD * fmaxf(fmaf(hb[(size_t)(r + 3) * 128], sc, sh), 0.f);
        mt += mA + mB + mC + mD;
    }
    v[c] = (a0 + a1) + (a2 + a3);
    if (c == 0) smt = mt;
    __syncthreads();

    if (c < OUTF) {
        float acc0 = smt * b2L[c], acc1 = 0.f, acc2 = 0.f, acc3 = 0.f;
        #pragma unroll 8
        for (int k = 0; k < 128; k += 4) {
            acc0 += v[k]     * W2L[(size_t)k * 64 + c];
            acc1 += v[k + 1] * W2L[(size_t)(k + 1) * 64 + c];
            acc2 += v[k + 2] * W2L[(size_t)(k + 2) * 64 + c];
            acc3 += v[k + 3] * W2L[(size_t)(k + 3) * 64 + c];
        }
        pe[(size_t)n * 64 + c] = (acc0 + acc1) + (acc2 + acc3);
    }
}

// ---------------------------------------------------------------------------
// Host-side launch
// ---------------------------------------------------------------------------
extern "C" void kernel_launch(void* const* d_in, const int* in_sizes, int n_in,
                              void* d_out, int out_size)
{
    const float* W        = (const float*)d_in[0];
    const float* mask     = (const float*)d_in[1];
    const int*   src      = (const int*)d_in[2];
    const int*   dst      = (const int*)d_in[3];
    const float* eps      = (const float*)d_in[4];
    const float* W1_first = (const float*)d_in[5];
    const float* b1_first = (const float*)d_in[6];
    const float* W1_rest  = (const float*)d_in[7];
    const float* b1_rest  = (const float*)d_in[8];
    const float* bn_gamma = (const float*)d_in[9];
    const float* bn_beta  = (const float*)d_in[10];
    const float* W2_mid   = (const float*)d_in[11];
    const float* b2_mid   = (const float*)d_in[12];
    const float* W2_last  = (const float*)d_in[13];
    const float* b2_last  = (const float*)d_in[14];
    float* pe = (float*)d_out;

    void *pHa, *pHb, *pY, *pW, *pStats, *pCf;
    cudaGetSymbolAddress(&pHa, g_Ha);
    cudaGetSymbolAddress(&pHb, g_Hb);
    cudaGetSymbolAddress(&pY, g_Y);
    cudaGetSymbolAddress(&pW, g_Wbf);
    cudaGetSymbolAddress(&pStats, g_stats);
    cudaGetSymbolAddress(&pCf, g_Cf);
    float* Ha = (float*)pHa;
    float* Hb = (float*)pHb;
    float* Yb = (float*)pY;
    __nv_bfloat16* Wbf = (__nv_bfloat16*)pW;
    float* st = (float*)pStats;
    float* Cf = (float*)pCf;

    const int smA16 = (192 * 40) * 2 + 512;                    // 15872
    const int smM   = 67584 + 67584 + 65536 + 1024;            // 201728

    cudaFuncSetAttribute(gin_A16, cudaFuncAttributeMaxDynamicSharedMemorySize, smA16);
    cudaFuncSetAttribute(gin_M,   cudaFuncAttributeMaxDynamicSharedMemorySize, smM);

    // Launch order: setup1(1), setup2(2), A16(3), M(4) <- ncu captures #4
    gin_setup1<<<50, 1024>>>(src, dst, W1_rest, W2_mid, b2_mid);
    gin_setup2<<<50, 1024>>>(W1_first);

    gin_A16<<<GRID_MAIN, 256, smA16>>>(W, Wbf + OFF_W1F, b1_first, eps,
                                       Ha, st, st + 128);

    float* bufs[2] = { Ha, Hb };
    for (int l = 0; l < 3; l++) {
        gin_M<<<GRID_M, 512, smM>>>(
            bufs[l & 1], Wbf + OFF_C(l),
            st + l * 256,
            bn_gamma + (size_t)l * HID, bn_beta + (size_t)l * HID,
            Yb);
        gin_Gg<<<NSUM, 256>>>(
            Yb, eps, l + 1,
            b1_rest + (size_t)l * HID,
            Cf + 3 * 16384 + l * 128,
            bufs[(l + 1) & 1],
            st + (l + 1) * 256, st + (l + 1) * 256 + 128);
    }

    gin_KL<<<NSUM, 128>>>(bufs[1],              // H4 (Ha->Hb->Ha->Hb)
                          st + 3 * 256,
                          bn_gamma + 3 * (size_t)HID, bn_beta + 3 * (size_t)HID,
                          mask, W2_last, b2_last, pe);
}